// round 3
// baseline (speedup 1.0000x reference)
#include <cuda_runtime.h>

// ---------------------------------------------------------------------------
// StarTransformerLayer  B=8 L=4096 H=256 NH=8 HD=32, 2 iterations.
// FP32 SIMT baseline exploiting concats redundancy:
//   - K/V of "before"/"after" reuse K/V(cur) rows (index tricks)
//   - K/V(x) computed once (x fixed across iters)
//   - center projections are B=8-row GEMVs
// Big GEMMs: fused-QKV(cur), ctx@Wo(+residual), fused rel-KV(cur), KV(x).
// ---------------------------------------------------------------------------

#define B_   8
#define L_   4096
#define H_   256
#define NPOS (B_*L_)              // 32768
#define SCALE_ 0.17677669529663689f   // 1/sqrt(32)

// ------------------------- scratch (device globals) ------------------------
__device__ float g_QKVc [NPOS*768];   // cur @ [Wq|Wk|Wv]  (sat)
__device__ float g_KVx  [NPOS*512];   // x   @ [Wk|Wv]     (sat, once)
__device__ float g_KVr  [NPOS*512];   // cur @ [Wk|Wv]     (rel)
__device__ float g_ctx  [NPOS*256];   // sat attention context
__device__ float g_satpre[NPOS*256];  // ctx@Wo + bo + cur
__device__ float g_cur  [NPOS*256];
__device__ float g_center[B_*H_];
__device__ float g_part [B_*32*H_];
__device__ float g_cenSat[B_*768];    // center @ sat [Wq|Wk|Wv]
__device__ float g_cenRel[B_*768];    // center @ rel [Wq|Wk|Wv]
__device__ float g_rctx [B_*H_];
__device__ float g_satW [256*768];
__device__ float g_relW [256*768];
__device__ float g_satBias[768];
__device__ float g_relBias[768];

// ------------------------------ helpers ------------------------------------
__device__ __forceinline__ float wsum(float v) {
    v += __shfl_xor_sync(0xffffffffu, v, 16);
    v += __shfl_xor_sync(0xffffffffu, v, 8);
    v += __shfl_xor_sync(0xffffffffu, v, 4);
    v += __shfl_xor_sync(0xffffffffu, v, 2);
    v += __shfl_xor_sync(0xffffffffu, v, 1);
    return v;
}

// ------------------------- weight/bias packing ------------------------------
__global__ void __launch_bounds__(256) pack_w(
    const float* __restrict__ Wq, const float* __restrict__ Wk, const float* __restrict__ Wv,
    const float* __restrict__ bq, const float* __restrict__ bk, const float* __restrict__ bv,
    float* __restrict__ Wp, float* __restrict__ bp)
{
    int idx = blockIdx.x * 256 + threadIdx.x;   // 0 .. 256*768-1
    int k = idx / 768, c = idx % 768;
    int sel = c >> 8, cc = c & 255;
    const float* W = (sel == 0) ? Wq : (sel == 1) ? Wk : Wv;
    Wp[idx] = W[k * 256 + cc];
    if (idx < 768) {
        const float* b = (sel == 0) ? bq : (sel == 1) ? bk : bv;
        bp[idx] = b[cc];
    }
}

// ------------------------------ mean over L ---------------------------------
__global__ void __launch_bounds__(256) mean_stage1(const float* __restrict__ x,
                                                   float* __restrict__ part)
{
    int s = blockIdx.x, n = blockIdx.y, c = threadIdx.x;
    const float* base = x + ((long)n * L_ + (long)s * 128) * H_ + c;
    float sum = 0.f;
    #pragma unroll 8
    for (int l = 0; l < 128; l++) sum += base[(long)l * H_];
    part[(n * 32 + s) * H_ + c] = sum;
}

__global__ void __launch_bounds__(256) mean_stage2(const float* __restrict__ part,
                                                   float* __restrict__ center)
{
    int n = blockIdx.x, c = threadIdx.x;
    float sum = 0.f;
    #pragma unroll
    for (int s = 0; s < 32; s++) sum += part[(n * 32 + s) * H_ + c];
    center[n * H_ + c] = sum * (1.f / (float)L_);
}

// ------------------------------- SGEMM --------------------------------------
// C[M,N] = A[M,256] @ W[256,N] + bias(N) (+ res[M,N]).  BM=BN=128, BK=8, 8x8/thread.
// All dims are exact tile multiples here; no bounds checks.
__global__ void __launch_bounds__(256, 2) sgemm_k256(
    const float* __restrict__ A, int lda,
    const float* __restrict__ W, int ldw,
    const float* __restrict__ bias,
    const float* __restrict__ res, int ldr,
    float* __restrict__ C, int ldc)
{
    __shared__ float As[8][128];
    __shared__ float Ws[8][128];

    const int m0 = blockIdx.y * 128;
    const int n0 = blockIdx.x * 128;
    const int tid  = threadIdx.x;
    const int aRow = tid >> 1;          // 0..127
    const int aCol = (tid & 1) * 4;     // 0 or 4
    const int wRow = tid >> 5;          // 0..7
    const int wCol = (tid & 31) * 4;    // 0..124
    const int tx = tid & 15, ty = tid >> 4;

    const float* Aptr = A + (long)(m0 + aRow) * lda + aCol;
    const float* Wptr = W + (long)wRow * ldw + n0 + wCol;

    float acc[8][8];
    #pragma unroll
    for (int i = 0; i < 8; i++)
        #pragma unroll
        for (int j = 0; j < 8; j++) acc[i][j] = 0.f;

    for (int k0 = 0; k0 < 256; k0 += 8) {
        float4 av = *(const float4*)(Aptr + k0);
        As[aCol + 0][aRow] = av.x;
        As[aCol + 1][aRow] = av.y;
        As[aCol + 2][aRow] = av.z;
        As[aCol + 3][aRow] = av.w;
        float4 wv = *(const float4*)(Wptr + (long)k0 * ldw);
        *(float4*)&Ws[wRow][wCol] = wv;
        __syncthreads();
        #pragma unroll
        for (int k = 0; k < 8; k++) {
            float a[8], b[8];
            #pragma unroll
            for (int i = 0; i < 8; i++) a[i] = As[k][ty * 8 + i];
            #pragma unroll
            for (int j = 0; j < 8; j++) b[j] = Ws[k][tx * 8 + j];
            #pragma unroll
            for (int i = 0; i < 8; i++)
                #pragma unroll
                for (int j = 0; j < 8; j++) acc[i][j] += a[i] * b[j];
        }
        __syncthreads();
    }

    #pragma unroll
    for (int i = 0; i < 8; i++) {
        long m = m0 + ty * 8 + i;
        #pragma unroll
        for (int j = 0; j < 8; j += 4) {
            int n = n0 + tx * 8 + j;
            float4 o;
            o.x = acc[i][j + 0]; o.y = acc[i][j + 1];
            o.z = acc[i][j + 2]; o.w = acc[i][j + 3];
            if (bias) {
                o.x += bias[n + 0]; o.y += bias[n + 1];
                o.z += bias[n + 2]; o.w += bias[n + 3];
            }
            if (res) {
                float4 r = *(const float4*)(res + m * ldr + n);
                o.x += r.x; o.y += r.y; o.z += r.z; o.w += r.w;
            }
            *(float4*)&C[m * ldc + n] = o;
        }
    }
}

// ---------------------- tiny projection: center @ Wpack ---------------------
// out[8,768] = center[8,256] @ Wp[256,768] + bp.  3 blocks per row (768/256).
__global__ void __launch_bounds__(256) cen_proj(
    const float* __restrict__ center, const float* __restrict__ Wp,
    const float* __restrict__ bp, float* __restrict__ out)
{
    __shared__ float sh[256];
    int idx = blockIdx.x * 256 + threadIdx.x;
    int r = idx / 768, c = idx % 768;
    sh[threadIdx.x] = center[r * 256 + threadIdx.x & 255 ? r * 256 + threadIdx.x % 256 : r * 256 + threadIdx.x]; // overwritten below; keep simple:
    sh[threadIdx.x] = center[r * 256 + threadIdx.x];
    __syncthreads();
    float s = bp[c];
    #pragma unroll 8
    for (int k = 0; k < 256; k++) s += sh[k] * Wp[k * 768 + c];
    out[idx] = s;
}

// --------------------------- sat attention ----------------------------------
// warp per position; lane = dim-in-head; 5 keys: before, cur, after, x, center.
__global__ void __launch_bounds__(256) sat_attn(
    const float* __restrict__ qkv,    // [NPOS,768]  Q|K|V of cur
    const float* __restrict__ kvx,    // [NPOS,512]  K|V of x
    const float* __restrict__ cen,    // [B,768]     Q|K|V of center
    float* __restrict__ ctx)          // [NPOS,256]
{
    int warp = (blockIdx.x * blockDim.x + threadIdx.x) >> 5;
    int lane = threadIdx.x & 31;
    if (warp >= NPOS) return;
    int n = warp >> 12;            // /L_
    int l = warp & (L_ - 1);
    long i  = warp;
    long rb = (long)n * L_ + ((l + 1 == L_) ? 0 : l + 1);   // before
    long ra = (long)n * L_ + ((l == 0) ? (L_ - 1) : 0);     // after

    #pragma unroll
    for (int h = 0; h < 8; h++) {
        int off = h * 32 + lane;
        float qv = qkv[i * 768 + off];
        float k0 = qkv[rb * 768 + 256 + off];
        float k1 = qkv[i  * 768 + 256 + off];
        float k2 = qkv[ra * 768 + 256 + off];
        float k3 = kvx[i * 512 + off];
        float k4 = cen[n * 768 + 256 + off];
        float s0 = wsum(qv * k0) * SCALE_;
        float s1 = wsum(qv * k1) * SCALE_;
        float s2 = wsum(qv * k2) * SCALE_;
        float s3 = wsum(qv * k3) * SCALE_;
        float s4 = wsum(qv * k4) * SCALE_;
        float m = fmaxf(fmaxf(fmaxf(s0, s1), fmaxf(s2, s3)), s4);
        float p0 = __expf(s0 - m), p1 = __expf(s1 - m), p2 = __expf(s2 - m);
        float p3 = __expf(s3 - m), p4 = __expf(s4 - m);
        float den = p0 + p1 + p2 + p3 + p4;
        float v0 = qkv[rb * 768 + 512 + off];
        float v1 = qkv[i  * 768 + 512 + off];
        float v2 = qkv[ra * 768 + 512 + off];
        float v3 = kvx[i * 512 + 256 + off];
        float v4 = cen[n * 768 + 512 + off];
        ctx[i * 256 + off] = (p0 * v0 + p1 * v1 + p2 * v2 + p3 * v3 + p4 * v4) / den;
    }
}

// ------------------------ relu + layernorm (per row) ------------------------
__global__ void __launch_bounds__(256) relu_ln(
    const float* __restrict__ in, const float* __restrict__ w,
    const float* __restrict__ b, float* __restrict__ out)
{
    long row = blockIdx.x;
    int c = threadIdx.x;
    float v = fmaxf(in[row * 256 + c], 0.f);
    __shared__ float sh[16];
    int lane = c & 31, wid = c >> 5;
    float rs = wsum(v), rq = wsum(v * v);
    if (lane == 0) { sh[wid] = rs; sh[8 + wid] = rq; }
    __syncthreads();
    float ts = 0.f, tq = 0.f;
    #pragma unroll
    for (int i = 0; i < 8; i++) { ts += sh[i]; tq += sh[8 + i]; }
    float u = ts * (1.f / 256.f);
    float var = tq * (1.f / 256.f) - u * u;
    out[row * 256 + c] = w[c] * (v - u) * rsqrtf(var + 1e-12f) + b[c];
}

// --------------------------- rel attention ----------------------------------
// block per (batch, head); 8 warps stride keys with online softmax; lane = dim.
__global__ void __launch_bounds__(256) rel_attn(
    const float* __restrict__ cen,   // [B,768] Q|K|V of center (rel weights)
    const float* __restrict__ kvr,   // [NPOS,512] K|V of cur (rel weights)
    float* __restrict__ rctx)        // [B,256]
{
    int n = blockIdx.x >> 3, h = blockIdx.x & 7;
    int w = threadIdx.x >> 5, lane = threadIdx.x & 31;
    int off = h * 32 + lane;
    float qv = cen[n * 768 + off];
    float m = -1e30f, s = 0.f, acc = 0.f;
    for (int t = w; t <= L_; t += 8) {
        float kv, vv;
        if (t == 0) { kv = cen[n * 768 + 256 + off]; vv = cen[n * 768 + 512 + off]; }
        else {
            long r = (long)n * L_ + (t - 1);
            kv = kvr[r * 512 + off];
            vv = kvr[r * 512 + 256 + off];
        }
        float d = wsum(qv * kv) * SCALE_;
        float mn = fmaxf(m, d);
        float eo = __expf(m - mn);
        float en = __expf(d - mn);
        s = s * eo + en;
        acc = acc * eo + en * vv;
        m = mn;
    }
    __shared__ float sm[8], ss[8], sacc[8][32];
    sacc[w][lane] = acc;
    if (lane == 0) { sm[w] = m; ss[w] = s; }
    __syncthreads();
    if (w == 0) {
        float M = sm[0];
        #pragma unroll
        for (int r = 1; r < 8; r++) M = fmaxf(M, sm[r]);
        float S = 0.f, A = 0.f;
        #pragma unroll
        for (int r = 0; r < 8; r++) {
            float f = __expf(sm[r] - M);
            S += ss[r] * f;
            A += sacc[r][lane] * f;
        }
        rctx[n * 256 + off] = A / S;
    }
}

// ---------------- rel output: rctx@Wo + bo + center, relu, LN ---------------
__global__ void __launch_bounds__(256) rel_out(
    const float* __restrict__ rctx, const float* __restrict__ Wo,
    const float* __restrict__ bo, float* __restrict__ center,
    const float* __restrict__ lnw, const float* __restrict__ lnb)
{
    int n = blockIdx.x, c = threadIdx.x;
    __shared__ float sa[256];
    sa[c] = rctx[n * 256 + c];
    __syncthreads();
    float o = bo[c] + center[n * 256 + c];
    #pragma unroll 8
    for (int k = 0; k < 256; k++) o += sa[k] * Wo[k * 256 + c];
    o = fmaxf(o, 0.f);
    __shared__ float sh[16];
    int lane = c & 31, wid = c >> 5;
    float rs = wsum(o), rq = wsum(o * o);
    if (lane == 0) { sh[wid] = rs; sh[8 + wid] = rq; }
    __syncthreads();
    float ts = 0.f, tq = 0.f;
    #pragma unroll
    for (int i = 0; i < 8; i++) { ts += sh[i]; tq += sh[8 + i]; }
    float u = ts * (1.f / 256.f);
    float var = tq * (1.f / 256.f) - u * u;
    center[n * 256 + c] = lnw[c] * (o - u) * rsqrtf(var + 1e-12f) + lnb[c];
}

// ------------------------------- output copy --------------------------------
__global__ void write_out(const float* __restrict__ cur, const float* __restrict__ center,
                          float* __restrict__ out, int ncur, int ntot)
{
    for (int i = blockIdx.x * blockDim.x + threadIdx.x; i < ntot; i += gridDim.x * blockDim.x) {
        if (i < ncur) out[i] = cur[i];
        else {
            int j = i - ncur;
            out[i] = (j < B_ * H_) ? center[j] : 0.f;
        }
    }
}

// ------------------------------- host side ----------------------------------
extern "C" void kernel_launch(void* const* d_in, const int* in_sizes, int n_in,
                              void* d_out, int out_size)
{
    const float* x    = (const float*)d_in[0];
    const float* sWq  = (const float*)d_in[1];
    const float* sbq  = (const float*)d_in[2];
    const float* sWk  = (const float*)d_in[3];
    const float* sbk  = (const float*)d_in[4];
    const float* sWv  = (const float*)d_in[5];
    const float* sbv  = (const float*)d_in[6];
    const float* sWo  = (const float*)d_in[7];
    const float* sbo  = (const float*)d_in[8];
    const float* rWq  = (const float*)d_in[9];
    const float* rbq  = (const float*)d_in[10];
    const float* rWk  = (const float*)d_in[11];
    const float* rbk  = (const float*)d_in[12];
    const float* rWv  = (const float*)d_in[13];
    const float* rbv  = (const float*)d_in[14];
    const float* rWo  = (const float*)d_in[15];
    const float* rbo  = (const float*)d_in[16];
    const float* slnw = (const float*)d_in[17];
    const float* slnb = (const float*)d_in[18];
    const float* rlnw = (const float*)d_in[19];
    const float* rlnb = (const float*)d_in[20];

    float *QKVc, *KVx, *KVr, *ctx, *satpre, *cur, *center, *part;
    float *cenSat, *cenRel, *rctx, *satW, *relW, *satB, *relB;
    cudaGetSymbolAddress((void**)&QKVc,   g_QKVc);
    cudaGetSymbolAddress((void**)&KVx,    g_KVx);
    cudaGetSymbolAddress((void**)&KVr,    g_KVr);
    cudaGetSymbolAddress((void**)&ctx,    g_ctx);
    cudaGetSymbolAddress((void**)&satpre, g_satpre);
    cudaGetSymbolAddress((void**)&cur,    g_cur);
    cudaGetSymbolAddress((void**)&center, g_center);
    cudaGetSymbolAddress((void**)&part,   g_part);
    cudaGetSymbolAddress((void**)&cenSat, g_cenSat);
    cudaGetSymbolAddress((void**)&cenRel, g_cenRel);
    cudaGetSymbolAddress((void**)&rctx,   g_rctx);
    cudaGetSymbolAddress((void**)&satW,   g_satW);
    cudaGetSymbolAddress((void**)&relW,   g_relW);
    cudaGetSymbolAddress((void**)&satB,   g_satBias);
    cudaGetSymbolAddress((void**)&relB,   g_relBias);

    // pack weights: [Wq|Wk|Wv] column-concat, row-major 256x768
    pack_w<<<768, 256>>>(sWq, sWk, sWv, sbq, sbk, sbv, satW, satB);
    pack_w<<<768, 256>>>(rWq, rWk, rWv, rbq, rbk, rbv, relW, relB);

    // center0 = mean_L(x)
    mean_stage1<<<dim3(32, B_), 256>>>(x, part);
    mean_stage2<<<B_, 256>>>(part, center);

    // K/V of x (once): cols 256..767 of sat pack
    sgemm_k256<<<dim3(4, NPOS / 128), 256>>>(x, 256, satW + 256, 768, satB + 256,
                                             nullptr, 0, KVx, 512);

    const float* curIn = x;
    for (int it = 0; it < 2; it++) {
        // center projections (sat)
        cen_proj<<<24, 256>>>(center, satW, satB, cenSat);
        // fused Q|K|V of cur
        sgemm_k256<<<dim3(6, NPOS / 128), 256>>>(curIn, 256, satW, 768, satB,
                                                 nullptr, 0, QKVc, 768);
        // 5-key attention
        sat_attn<<<NPOS / 8, 256>>>(QKVc, KVx, cenSat, ctx);
        // ctx @ Wo + bo + residual(cur)
        sgemm_k256<<<dim3(2, NPOS / 128), 256>>>(ctx, 256, sWo, 256, sbo,
                                                 curIn, 256, satpre, 256);
        // relu + LN -> new cur
        relu_ln<<<NPOS, 256>>>(satpre, slnw, slnb, cur);

        // center projections (rel) — uses pre-update center
        cen_proj<<<24, 256>>>(center, relW, relB, cenRel);
        // fused K|V of new cur (rel)
        sgemm_k256<<<dim3(4, NPOS / 128), 256>>>(cur, 256, relW + 256, 768, relB + 256,
                                                 nullptr, 0, KVr, 512);
        // 1-query attention over L+1 keys
        rel_attn<<<B_ * 8, 256>>>(cenRel, KVr, rctx);
        // rctx @ Wo + bo + center residual, relu, LN -> new center
        rel_out<<<B_, 256>>>(rctx, rWo, rbo, center, rlnw, rlnb);

        curIn = cur;
    }

    write_out<<<2048, 256>>>(cur, center, (float*)d_out, NPOS * H_, out_size);
}

// round 6
// speedup vs baseline: 1.4530x; 1.4530x over previous
#include <cuda_runtime.h>
#include <cuda_bf16.h>
#include <cstdint>

// ---------------------------------------------------------------------------
// StarTransformerLayer  B=8 L=4096 H=256 NH=8 HD=32, 2 iterations.
// Round 6: harness PTX target is sm_103 (no 'a' feature) -> tcgen05 is
// unavailable. Big GEMMs use mma.sync.aligned.m16n8k16 bf16 (HMMA) with
// fp32->bf16 hi/lo 3-product compensation. Everything else = round-3 pass.
// ---------------------------------------------------------------------------

#define B_   8
#define L_   4096
#define H_   256
#define NPOS (B_*L_)              // 32768
#define SCALE_ 0.17677669529663689f   // 1/sqrt(32)

// ------------------------- scratch (device globals) ------------------------
__device__ float g_QKVc [NPOS*768];
__device__ float g_KVx  [NPOS*512];
__device__ float g_KVr  [NPOS*512];
__device__ float g_ctx  [NPOS*256];
__device__ float g_satpre[NPOS*256];
__device__ float g_cur  [NPOS*256];
__device__ float g_center[B_*H_];
__device__ float g_part [B_*32*H_];
__device__ float g_cenSat[B_*768];
__device__ float g_cenRel[B_*768];
__device__ float g_rctx [B_*H_];
__device__ float g_satW [256*768];
__device__ float g_relW [256*768];
__device__ float g_satBias[768];
__device__ float g_relBias[768];
// transposed + split weights: [N,256] K-major bf16 (B^T for mma row.col)
__device__ __nv_bfloat16 g_sWtH[768*256];
__device__ __nv_bfloat16 g_sWtL[768*256];
__device__ __nv_bfloat16 g_rWtH[768*256];
__device__ __nv_bfloat16 g_rWtL[768*256];
__device__ __nv_bfloat16 g_sWoTH[256*256];
__device__ __nv_bfloat16 g_sWoTL[256*256];

// ------------------------------ helpers -------------------------------------
__device__ __forceinline__ uint32_t su32(const void* p) {
    return (uint32_t)__cvta_generic_to_shared(p);
}
__device__ __forceinline__ uint32_t swz(uint32_t o) {    // SW128-style xor
    return o ^ ((o >> 3) & 0x70);
}
__device__ __forceinline__ uint32_t pk_bf2(__nv_bfloat16 a, __nv_bfloat16 b) {
    __nv_bfloat162 t; t.x = a; t.y = b;
    return *reinterpret_cast<uint32_t*>(&t);
}
__device__ __forceinline__ void ldm4(uint32_t* r, uint32_t addr) {
    asm volatile("ldmatrix.sync.aligned.m8n8.x4.shared.b16 {%0,%1,%2,%3}, [%4];"
                 : "=r"(r[0]), "=r"(r[1]), "=r"(r[2]), "=r"(r[3]) : "r"(addr));
}
__device__ __forceinline__ void mma16816(float* d, const uint32_t* a,
                                         uint32_t b0, uint32_t b1) {
    asm volatile(
        "mma.sync.aligned.m16n8k16.row.col.f32.bf16.bf16.f32 "
        "{%0,%1,%2,%3}, {%4,%5,%6,%7}, {%8,%9}, {%0,%1,%2,%3};"
        : "+f"(d[0]), "+f"(d[1]), "+f"(d[2]), "+f"(d[3])
        : "r"(a[0]), "r"(a[1]), "r"(a[2]), "r"(a[3]), "r"(b0), "r"(b1));
}
__device__ __forceinline__ float wsum(float v) {
    v += __shfl_xor_sync(0xffffffffu, v, 16);
    v += __shfl_xor_sync(0xffffffffu, v, 8);
    v += __shfl_xor_sync(0xffffffffu, v, 4);
    v += __shfl_xor_sync(0xffffffffu, v, 2);
    v += __shfl_xor_sync(0xffffffffu, v, 1);
    return v;
}

// =========================== HMMA GEMM ======================================
// C[M,N] = A[M,256](fp32) @ W[256,N] + bias (+ res).  B = W^T in bf16 hi/lo.
// Tile 128x128, K chunks of 64 in smem, 3-product compensation, 2 CTA/SM.
#define GSMEM_DYN (65536 + 1024)

__global__ void __launch_bounds__(256, 2) gemm_mma(
    const float* __restrict__ A, int lda,
    const __nv_bfloat16* __restrict__ Bh,   // [N,256] K-major
    const __nv_bfloat16* __restrict__ Bl,
    const float* __restrict__ bias,
    const float* __restrict__ res, int ldr,
    float* __restrict__ C, int ldc)
{
    extern __shared__ char smem_raw[];
    char* smem = (char*)(((uintptr_t)smem_raw + 1023) & ~(uintptr_t)1023);
    char* sAh = smem;            // 128 x 64 bf16, 128B rows, swizzled
    char* sAl = smem + 16384;
    char* sBh = smem + 32768;    // 128(n) x 64(k) bf16
    char* sBl = smem + 49152;
    const uint32_t uAh = su32(sAh), uAl = su32(sAl);
    const uint32_t uBh = su32(sBh), uBl = su32(sBl);

    const int tid  = threadIdx.x;
    const int wid  = tid >> 5;
    const int lane = tid & 31;
    const int wm = wid >> 2;        // 0..1  (64-row block)
    const int wn = wid & 3;         // 0..3  (32-col block)

    const int m0 = blockIdx.y * 128;
    const int n0 = blockIdx.x * 128;
    const int row  = tid >> 1;      // 0..127 (fill row)
    const int half = tid & 1;

    float acc[4][4][4];
    #pragma unroll
    for (int i = 0; i < 4; i++)
        #pragma unroll
        for (int j = 0; j < 4; j++)
            #pragma unroll
            for (int t = 0; t < 4; t++) acc[i][j][t] = 0.f;

    // ldmatrix lane addressing (constant per thread)
    const int aR = lane & 15;                       // A frag row within 16
    const int aC16 = (lane >> 4);                   // 0/1 -> +8 cols
    const int bN = (lane & 7) + ((lane >> 1) & 8);  // B frag n within 16
    const int bK8 = (lane >> 3) & 1;                // 0/1 -> +8 k

    for (int c = 0; c < 4; c++) {
        // ---- fill A (fp32 -> hi/lo bf16) ----
        const float* ap = A + (long)(m0 + row) * lda + c * 64 + half * 32;
        #pragma unroll
        for (int i = 0; i < 8; i++) {
            float4 v = *(const float4*)(ap + i * 4);
            __nv_bfloat16 hx = __float2bfloat16(v.x);
            __nv_bfloat16 hy = __float2bfloat16(v.y);
            __nv_bfloat16 hz = __float2bfloat16(v.z);
            __nv_bfloat16 hw = __float2bfloat16(v.w);
            __nv_bfloat16 lx = __float2bfloat16(v.x - __bfloat162float(hx));
            __nv_bfloat16 ly = __float2bfloat16(v.y - __bfloat162float(hy));
            __nv_bfloat16 lz = __float2bfloat16(v.z - __bfloat162float(hz));
            __nv_bfloat16 lw = __float2bfloat16(v.w - __bfloat162float(hw));
            uint32_t sw = swz(row * 128 + (half * 32 + i * 4) * 2);
            uint2 hvv; hvv.x = pk_bf2(hx, hy); hvv.y = pk_bf2(hz, hw);
            uint2 lvv; lvv.x = pk_bf2(lx, ly); lvv.y = pk_bf2(lz, lw);
            *(uint2*)(sAh + sw) = hvv;
            *(uint2*)(sAl + sw) = lvv;
        }
        // ---- fill B (pre-split bf16 copy) ----
        {
            const __nv_bfloat16* bph = Bh + (long)(n0 + row) * 256 + c * 64 + half * 32;
            const __nv_bfloat16* bpl = Bl + (long)(n0 + row) * 256 + c * 64 + half * 32;
            #pragma unroll
            for (int j = 0; j < 4; j++) {
                uint32_t sw = swz(row * 128 + half * 64 + j * 16);
                *(uint4*)(sBh + sw) = *(const uint4*)(bph + j * 8);
                *(uint4*)(sBl + sw) = *(const uint4*)(bpl + j * 8);
            }
        }
        __syncthreads();

        // ---- MMA over 4 k16 steps ----
        #pragma unroll
        for (int ks = 0; ks < 4; ks++) {
            const int k0 = ks * 16;
            uint32_t bh[2][4], bl[2][4];
            #pragma unroll
            for (int ng = 0; ng < 2; ng++) {
                uint32_t boff = swz((uint32_t)(wn * 32 + ng * 16 + bN) * 128
                                    + (k0 + bK8 * 8) * 2);
                ldm4(bh[ng], uBh + boff);
                ldm4(bl[ng], uBl + boff);
            }
            #pragma unroll
            for (int mt = 0; mt < 4; mt++) {
                uint32_t ah[4], al[4];
                uint32_t aoff = swz((uint32_t)(wm * 64 + mt * 16 + aR) * 128
                                    + (k0 + aC16 * 8) * 2);
                ldm4(ah, uAh + aoff);
                ldm4(al, uAl + aoff);
                #pragma unroll
                for (int nt = 0; nt < 4; nt++) {
                    const int ng = nt >> 1, sb = (nt & 1) * 2;
                    mma16816(acc[mt][nt], ah, bh[ng][sb], bh[ng][sb + 1]);
                    mma16816(acc[mt][nt], ah, bl[ng][sb], bl[ng][sb + 1]);
                    mma16816(acc[mt][nt], al, bh[ng][sb], bh[ng][sb + 1]);
                }
            }
        }
        __syncthreads();
    }

    // ---- epilogue: registers -> gmem with fused bias/residual ----
    const int er = lane >> 2;
    const int ec = (lane & 3) * 2;
    #pragma unroll
    for (int mt = 0; mt < 4; mt++) {
        #pragma unroll
        for (int nt = 0; nt < 4; nt++) {
            const long m = m0 + wm * 64 + mt * 16 + er;
            const int  n = n0 + wn * 32 + nt * 8 + ec;
            float bx = bias[n], by = bias[n + 1];
            float2 o0, o1;
            o0.x = acc[mt][nt][0] + bx; o0.y = acc[mt][nt][1] + by;
            o1.x = acc[mt][nt][2] + bx; o1.y = acc[mt][nt][3] + by;
            if (res) {
                float2 r0 = *(const float2*)(res + m * ldr + n);
                float2 r1 = *(const float2*)(res + (m + 8) * ldr + n);
                o0.x += r0.x; o0.y += r0.y;
                o1.x += r1.x; o1.y += r1.y;
            }
            *(float2*)(C + m * ldc + n) = o0;
            *(float2*)(C + (m + 8) * ldc + n) = o1;
        }
    }
}

// ------------------------- weight/bias packing ------------------------------
__global__ void __launch_bounds__(256) pack_w(
    const float* __restrict__ Wq, const float* __restrict__ Wk, const float* __restrict__ Wv,
    const float* __restrict__ bq, const float* __restrict__ bk, const float* __restrict__ bv,
    float* __restrict__ Wp, float* __restrict__ bp)
{
    int idx = blockIdx.x * 256 + threadIdx.x;
    int k = idx / 768, c = idx % 768;
    int sel = c >> 8, cc = c & 255;
    const float* W = (sel == 0) ? Wq : (sel == 1) ? Wk : Wv;
    Wp[idx] = W[k * 256 + cc];
    if (idx < 768) {
        const float* b = (sel == 0) ? bq : (sel == 1) ? bk : bv;
        bp[idx] = b[cc];
    }
}

// Wt[n][k] = Wsel[k][n&255], split bf16 hi/lo.
__global__ void __launch_bounds__(256) pack_wt(
    const float* __restrict__ W0, const float* __restrict__ W1, const float* __restrict__ W2,
    __nv_bfloat16* __restrict__ th, __nv_bfloat16* __restrict__ tl)
{
    int idx = blockIdx.x * 256 + threadIdx.x;
    int n = idx >> 8, k = idx & 255;
    int sel = n >> 8, nc = n & 255;
    const float* W = (sel == 0) ? W0 : (sel == 1) ? W1 : W2;
    float v = W[k * 256 + nc];
    __nv_bfloat16 h = __float2bfloat16(v);
    th[idx] = h;
    tl[idx] = __float2bfloat16(v - __bfloat162float(h));
}

// ------------------------------ mean over L ---------------------------------
__global__ void __launch_bounds__(256) mean_stage1(const float* __restrict__ x,
                                                   float* __restrict__ part)
{
    int s = blockIdx.x, n = blockIdx.y, c = threadIdx.x;
    const float* base = x + ((long)n * L_ + (long)s * 128) * H_ + c;
    float sum = 0.f;
    #pragma unroll 8
    for (int l = 0; l < 128; l++) sum += base[(long)l * H_];
    part[(n * 32 + s) * H_ + c] = sum;
}

__global__ void __launch_bounds__(256) mean_stage2(const float* __restrict__ part,
                                                   float* __restrict__ center)
{
    int n = blockIdx.x, c = threadIdx.x;
    float sum = 0.f;
    #pragma unroll
    for (int s = 0; s < 32; s++) sum += part[(n * 32 + s) * H_ + c];
    center[n * H_ + c] = sum * (1.f / (float)L_);
}

// ---------------------- tiny projection: center @ Wpack ---------------------
__global__ void __launch_bounds__(256) cen_proj(
    const float* __restrict__ center, const float* __restrict__ Wp,
    const float* __restrict__ bp, float* __restrict__ out)
{
    __shared__ float sh[256];
    int idx = blockIdx.x * 256 + threadIdx.x;
    int r = idx / 768, c = idx % 768;
    sh[threadIdx.x] = center[r * 256 + threadIdx.x];
    __syncthreads();
    float s = bp[c];
    #pragma unroll 8
    for (int k = 0; k < 256; k++) s += sh[k] * Wp[k * 768 + c];
    out[idx] = s;
}

// --------------------------- sat attention ----------------------------------
__global__ void __launch_bounds__(256) sat_attn(
    const float* __restrict__ qkv,    // [NPOS,768]
    const float* __restrict__ kvx,    // [NPOS,512]
    const float* __restrict__ cen,    // [B,768]
    float* __restrict__ ctx)          // [NPOS,256]
{
    int warp = (blockIdx.x * blockDim.x + threadIdx.x) >> 5;
    int lane = threadIdx.x & 31;
    if (warp >= NPOS) return;
    int n = warp >> 12;
    int l = warp & (L_ - 1);
    long i  = warp;
    long rb = (long)n * L_ + ((l + 1 == L_) ? 0 : l + 1);
    long ra = (long)n * L_ + ((l == 0) ? (L_ - 1) : 0);

    #pragma unroll
    for (int h = 0; h < 8; h++) {
        int off = h * 32 + lane;
        float qv = qkv[i * 768 + off];
        float k0 = qkv[rb * 768 + 256 + off];
        float k1 = qkv[i  * 768 + 256 + off];
        float k2 = qkv[ra * 768 + 256 + off];
        float k3 = kvx[i * 512 + off];
        float k4 = cen[n * 768 + 256 + off];
        float s0 = wsum(qv * k0) * SCALE_;
        float s1 = wsum(qv * k1) * SCALE_;
        float s2 = wsum(qv * k2) * SCALE_;
        float s3 = wsum(qv * k3) * SCALE_;
        float s4 = wsum(qv * k4) * SCALE_;
        float m = fmaxf(fmaxf(fmaxf(s0, s1), fmaxf(s2, s3)), s4);
        float p0 = __expf(s0 - m), p1 = __expf(s1 - m), p2 = __expf(s2 - m);
        float p3 = __expf(s3 - m), p4 = __expf(s4 - m);
        float den = p0 + p1 + p2 + p3 + p4;
        float v0 = qkv[rb * 768 + 512 + off];
        float v1 = qkv[i  * 768 + 512 + off];
        float v2 = qkv[ra * 768 + 512 + off];
        float v3 = kvx[i * 512 + 256 + off];
        float v4 = cen[n * 768 + 512 + off];
        ctx[i * 256 + off] = (p0 * v0 + p1 * v1 + p2 * v2 + p3 * v3 + p4 * v4) / den;
    }
}

// ------------------------ relu + layernorm (per row) ------------------------
__global__ void __launch_bounds__(256) relu_ln(
    const float* __restrict__ in, const float* __restrict__ w,
    const float* __restrict__ b, float* __restrict__ out)
{
    long row = blockIdx.x;
    int c = threadIdx.x;
    float v = fmaxf(in[row * 256 + c], 0.f);
    __shared__ float sh[16];
    int lane = c & 31, wid = c >> 5;
    float rs = wsum(v), rq = wsum(v * v);
    if (lane == 0) { sh[wid] = rs; sh[8 + wid] = rq; }
    __syncthreads();
    float ts = 0.f, tq = 0.f;
    #pragma unroll
    for (int i = 0; i < 8; i++) { ts += sh[i]; tq += sh[8 + i]; }
    float u = ts * (1.f / 256.f);
    float var = tq * (1.f / 256.f) - u * u;
    out[row * 256 + c] = w[c] * (v - u) * rsqrtf(var + 1e-12f) + b[c];
}

// --------------------------- rel attention ----------------------------------
__global__ void __launch_bounds__(256) rel_attn(
    const float* __restrict__ cen,   // [B,768]
    const float* __restrict__ kvr,   // [NPOS,512]
    float* __restrict__ rctx)        // [B,256]
{
    int n = blockIdx.x >> 3, h = blockIdx.x & 7;
    int w = threadIdx.x >> 5, lane = threadIdx.x & 31;
    int off = h * 32 + lane;
    float qv = cen[n * 768 + off];
    float m = -1e30f, s = 0.f, acc = 0.f;
    for (int t = w; t <= L_; t += 8) {
        float kv, vv;
        if (t == 0) { kv = cen[n * 768 + 256 + off]; vv = cen[n * 768 + 512 + off]; }
        else {
            long r = (long)n * L_ + (t - 1);
            kv = kvr[r * 512 + off];
            vv = kvr[r * 512 + 256 + off];
        }
        float d = wsum(qv * kv) * SCALE_;
        float mn = fmaxf(m, d);
        float eo = __expf(m - mn);
        float en = __expf(d - mn);
        s = s * eo + en;
        acc = acc * eo + en * vv;
        m = mn;
    }
    __shared__ float sm[8], ss[8], sacc[8][32];
    sacc[w][lane] = acc;
    if (lane == 0) { sm[w] = m; ss[w] = s; }
    __syncthreads();
    if (w == 0) {
        float M = sm[0];
        #pragma unroll
        for (int r = 1; r < 8; r++) M = fmaxf(M, sm[r]);
        float S = 0.f, A = 0.f;
        #pragma unroll
        for (int r = 0; r < 8; r++) {
            float f = __expf(sm[r] - M);
            S += ss[r] * f;
            A += sacc[r][lane] * f;
        }
        rctx[n * 256 + off] = A / S;
    }
}

// ---------------- rel output: rctx@Wo + bo + center, relu, LN ---------------
__global__ void __launch_bounds__(256) rel_out(
    const float* __restrict__ rctx, const float* __restrict__ Wo,
    const float* __restrict__ bo, float* __restrict__ center,
    const float* __restrict__ lnw, const float* __restrict__ lnb)
{
    int n = blockIdx.x, c = threadIdx.x;
    __shared__ float sa[256];
    sa[c] = rctx[n * 256 + c];
    __syncthreads();
    float o = bo[c] + center[n * 256 + c];
    #pragma unroll 8
    for (int k = 0; k < 256; k++) o += sa[k] * Wo[k * 256 + c];
    o = fmaxf(o, 0.f);
    __shared__ float sh[16];
    int lane = c & 31, wid = c >> 5;
    float rs = wsum(o), rq = wsum(o * o);
    if (lane == 0) { sh[wid] = rs; sh[8 + wid] = rq; }
    __syncthreads();
    float ts = 0.f, tq = 0.f;
    #pragma unroll
    for (int i = 0; i < 8; i++) { ts += sh[i]; tq += sh[8 + i]; }
    float u = ts * (1.f / 256.f);
    float var = tq * (1.f / 256.f) - u * u;
    center[n * 256 + c] = lnw[c] * (o - u) * rsqrtf(var + 1e-12f) + lnb[c];
}

// ------------------------------- output copy --------------------------------
__global__ void write_out(const float* __restrict__ cur, const float* __restrict__ center,
                          float* __restrict__ out, int ncur, int ntot)
{
    for (int i = blockIdx.x * blockDim.x + threadIdx.x; i < ntot; i += gridDim.x * blockDim.x) {
        if (i < ncur) out[i] = cur[i];
        else {
            int j = i - ncur;
            out[i] = (j < B_ * H_) ? center[j] : 0.f;
        }
    }
}

// ------------------------------- host side ----------------------------------
extern "C" void kernel_launch(void* const* d_in, const int* in_sizes, int n_in,
                              void* d_out, int out_size)
{
    const float* x    = (const float*)d_in[0];
    const float* sWq  = (const float*)d_in[1];
    const float* sbq  = (const float*)d_in[2];
    const float* sWk  = (const float*)d_in[3];
    const float* sbk  = (const float*)d_in[4];
    const float* sWv  = (const float*)d_in[5];
    const float* sbv  = (const float*)d_in[6];
    const float* sWo  = (const float*)d_in[7];
    const float* sbo  = (const float*)d_in[8];
    const float* rWq  = (const float*)d_in[9];
    const float* rbq  = (const float*)d_in[10];
    const float* rWk  = (const float*)d_in[11];
    const float* rbk  = (const float*)d_in[12];
    const float* rWv  = (const float*)d_in[13];
    const float* rbv  = (const float*)d_in[14];
    const float* rWo  = (const float*)d_in[15];
    const float* rbo  = (const float*)d_in[16];
    const float* slnw = (const float*)d_in[17];
    const float* slnb = (const float*)d_in[18];
    const float* rlnw = (const float*)d_in[19];
    const float* rlnb = (const float*)d_in[20];

    float *QKVc, *KVx, *KVr, *ctx, *satpre, *cur, *center, *part;
    float *cenSat, *cenRel, *rctx, *satW, *relW, *satB, *relB;
    __nv_bfloat16 *sWtH, *sWtL, *rWtH, *rWtL, *sWoTH, *sWoTL;
    cudaGetSymbolAddress((void**)&QKVc,   g_QKVc);
    cudaGetSymbolAddress((void**)&KVx,    g_KVx);
    cudaGetSymbolAddress((void**)&KVr,    g_KVr);
    cudaGetSymbolAddress((void**)&ctx,    g_ctx);
    cudaGetSymbolAddress((void**)&satpre, g_satpre);
    cudaGetSymbolAddress((void**)&cur,    g_cur);
    cudaGetSymbolAddress((void**)&center, g_center);
    cudaGetSymbolAddress((void**)&part,   g_part);
    cudaGetSymbolAddress((void**)&cenSat, g_cenSat);
    cudaGetSymbolAddress((void**)&cenRel, g_cenRel);
    cudaGetSymbolAddress((void**)&rctx,   g_rctx);
    cudaGetSymbolAddress((void**)&satW,   g_satW);
    cudaGetSymbolAddress((void**)&relW,   g_relW);
    cudaGetSymbolAddress((void**)&satB,   g_satBias);
    cudaGetSymbolAddress((void**)&relB,   g_relBias);
    cudaGetSymbolAddress((void**)&sWtH,   g_sWtH);
    cudaGetSymbolAddress((void**)&sWtL,   g_sWtL);
    cudaGetSymbolAddress((void**)&rWtH,   g_rWtH);
    cudaGetSymbolAddress((void**)&rWtL,   g_rWtL);
    cudaGetSymbolAddress((void**)&sWoTH,  g_sWoTH);
    cudaGetSymbolAddress((void**)&sWoTL,  g_sWoTL);

    cudaFuncSetAttribute(gemm_mma, cudaFuncAttributeMaxDynamicSharedMemorySize, GSMEM_DYN);

    // packs
    pack_w<<<768, 256>>>(sWq, sWk, sWv, sbq, sbk, sbv, satW, satB);
    pack_w<<<768, 256>>>(rWq, rWk, rWv, rbq, rbk, rbv, relW, relB);
    pack_wt<<<768, 256>>>(sWq, sWk, sWv, sWtH, sWtL);
    pack_wt<<<768, 256>>>(rWq, rWk, rWv, rWtH, rWtL);
    pack_wt<<<256, 256>>>(sWo, sWo, sWo, sWoTH, sWoTL);

    // center0 = mean_L(x)
    mean_stage1<<<dim3(32, B_), 256>>>(x, part);
    mean_stage2<<<B_, 256>>>(part, center);

    // K/V of x (once): rows 256..767 of sat pack
    gemm_mma<<<dim3(4, NPOS / 128), 256, GSMEM_DYN>>>(
        x, 256, sWtH + 256 * 256, sWtL + 256 * 256, satB + 256, nullptr, 0, KVx, 512);

    const float* curIn = x;
    for (int it = 0; it < 2; it++) {
        cen_proj<<<24, 256>>>(center, satW, satB, cenSat);
        gemm_mma<<<dim3(6, NPOS / 128), 256, GSMEM_DYN>>>(
            curIn, 256, sWtH, sWtL, satB, nullptr, 0, QKVc, 768);
        sat_attn<<<NPOS / 8, 256>>>(QKVc, KVx, cenSat, ctx);
        gemm_mma<<<dim3(2, NPOS / 128), 256, GSMEM_DYN>>>(
            ctx, 256, sWoTH, sWoTL, sbo, curIn, 256, satpre, 256);
        relu_ln<<<NPOS, 256>>>(satpre, slnw, slnb, cur);

        cen_proj<<<24, 256>>>(center, relW, relB, cenRel);
        gemm_mma<<<dim3(4, NPOS / 128), 256, GSMEM_DYN>>>(
            cur, 256, rWtH + 256 * 256, rWtL + 256 * 256, relB + 256, nullptr, 0, KVr, 512);
        rel_attn<<<B_ * 8, 256>>>(cenRel, KVr, rctx);
        rel_out<<<B_, 256>>>(rctx, rWo, rbo, center, rlnw, rlnb);

        curIn = cur;
    }

    write_out<<<2048, 256>>>(cur, center, (float*)d_out, NPOS * H_, out_size);
}

// round 8
// speedup vs baseline: 1.7452x; 1.2011x over previous
#include <cuda_runtime.h>
#include <cuda_bf16.h>
#include <cstdint>

// ---------------------------------------------------------------------------
// StarTransformerLayer  B=8 L=4096 H=256 NH=8 HD=32, 2 iterations.
// Round 7: HMMA GEMM with pre-split bf16 hi/lo A operands (split fused into
// producers), cp.async 2-stage pipeline (K-chunk 32), SW64 swizzle,
// 3-product fp32 compensation.  PTX target sm_103 (no tcgen05).
// ---------------------------------------------------------------------------

#define B_   8
#define L_   4096
#define H_   256
#define NPOS (B_*L_)              // 32768
#define SCALE_ 0.17677669529663689f   // 1/sqrt(32)

// ------------------------- scratch (device globals) ------------------------
__device__ float g_QKVc [NPOS*768];
__device__ float g_KVx  [NPOS*512];
__device__ float g_KVr  [NPOS*512];
__device__ float g_satpre[NPOS*256];
__device__ float g_cur  [NPOS*256];
__device__ float g_center[B_*H_];
__device__ float g_part [B_*32*H_];
__device__ float g_cenSat[B_*768];
__device__ float g_cenRel[B_*768];
__device__ float g_rctx [B_*H_];
__device__ float g_satW [256*768];
__device__ float g_relW [256*768];
__device__ float g_satBias[768];
__device__ float g_relBias[768];
// pre-split bf16 hi/lo activations (GEMM A operands)
__device__ __nv_bfloat16 g_xH  [NPOS*256];
__device__ __nv_bfloat16 g_xL  [NPOS*256];
__device__ __nv_bfloat16 g_ctxH[NPOS*256];
__device__ __nv_bfloat16 g_ctxL[NPOS*256];
__device__ __nv_bfloat16 g_curH[NPOS*256];
__device__ __nv_bfloat16 g_curL[NPOS*256];
// transposed + split weights: [N,256] K-major bf16
__device__ __nv_bfloat16 g_sWtH[768*256];
__device__ __nv_bfloat16 g_sWtL[768*256];
__device__ __nv_bfloat16 g_rWtH[768*256];
__device__ __nv_bfloat16 g_rWtL[768*256];
__device__ __nv_bfloat16 g_sWoTH[256*256];
__device__ __nv_bfloat16 g_sWoTL[256*256];

// ------------------------------ helpers -------------------------------------
__device__ __forceinline__ uint32_t su32(const void* p) {
    return (uint32_t)__cvta_generic_to_shared(p);
}
__device__ __forceinline__ uint32_t swz64(uint32_t o) {   // 64B-row swizzle
    return o ^ ((o >> 3) & 0x30);
}
__device__ __forceinline__ void cpa16(uint32_t saddr, const void* g) {
    asm volatile("cp.async.cg.shared.global [%0], [%1], 16;"
                 :: "r"(saddr), "l"(g));
}
__device__ __forceinline__ void ldm4(uint32_t* r, uint32_t addr) {
    asm volatile("ldmatrix.sync.aligned.m8n8.x4.shared.b16 {%0,%1,%2,%3}, [%4];"
                 : "=r"(r[0]), "=r"(r[1]), "=r"(r[2]), "=r"(r[3]) : "r"(addr));
}
__device__ __forceinline__ void mma16816(float* d, const uint32_t* a,
                                         uint32_t b0, uint32_t b1) {
    asm volatile(
        "mma.sync.aligned.m16n8k16.row.col.f32.bf16.bf16.f32 "
        "{%0,%1,%2,%3}, {%4,%5,%6,%7}, {%8,%9}, {%0,%1,%2,%3};"
        : "+f"(d[0]), "+f"(d[1]), "+f"(d[2]), "+f"(d[3])
        : "r"(a[0]), "r"(a[1]), "r"(a[2]), "r"(a[3]), "r"(b0), "r"(b1));
}
__device__ __forceinline__ float wsum(float v) {
    v += __shfl_xor_sync(0xffffffffu, v, 16);
    v += __shfl_xor_sync(0xffffffffu, v, 8);
    v += __shfl_xor_sync(0xffffffffu, v, 4);
    v += __shfl_xor_sync(0xffffffffu, v, 2);
    v += __shfl_xor_sync(0xffffffffu, v, 1);
    return v;
}

// =========================== HMMA GEMM ======================================
// C[M,N] = (Ah+Al)[M,256] @ (Bh+Bl)^T + bias (+ res fp32).
// Tile 128x128.  K chunks of 32, 2-stage cp.async pipeline.  2 CTA/SM.
#define KC_    32
#define NCH_   8
#define STGB_  32768           // 4 arrays x 8KB per stage
#define GSMEM_DYN (2*STGB_ + 1024)

__global__ void __launch_bounds__(256, 2) gemm_mma(
    const __nv_bfloat16* __restrict__ Ah,   // [M,256]
    const __nv_bfloat16* __restrict__ Al,
    const __nv_bfloat16* __restrict__ Bh,   // [N,256] K-major
    const __nv_bfloat16* __restrict__ Bl,
    const float* __restrict__ bias,
    const float* __restrict__ res, int ldr,
    float* __restrict__ C, int ldc)
{
    extern __shared__ char smem_raw[];
    char* smem = (char*)(((uintptr_t)smem_raw + 1023) & ~(uintptr_t)1023);
    const uint32_t sbase = su32(smem);

    const int tid  = threadIdx.x;
    const int wid  = tid >> 5;
    const int lane = tid & 31;
    const int wm = wid >> 2;        // 0..1
    const int wn = wid & 3;         // 0..3
    const int m0 = blockIdx.y * 128;
    const int n0 = blockIdx.x * 128;

    // fill indexing: 512 16B-chunks per 8KB array, 2 per thread
    const int r0f = (tid) >> 2,   q0f = (tid) & 3;
    const int r1f = (tid + 256) >> 2, q1f = (tid + 256) & 3;

    float acc[4][4][4];
    #pragma unroll
    for (int i = 0; i < 4; i++)
        #pragma unroll
        for (int j = 0; j < 4; j++)
            #pragma unroll
            for (int t = 0; t < 4; t++) acc[i][j][t] = 0.f;

    const int aR = lane & 15;
    const int aC16 = lane >> 4;
    const int bN = (lane & 7) + ((lane >> 1) & 8);
    const int bK8 = (lane >> 3) & 1;

    // per-stage smem array offsets
    auto load_stage = [&](int c, int s) {
        uint32_t st = sbase + (uint32_t)s * STGB_;
        const uint32_t so0 = swz64(r0f * 64 + q0f * 16);
        const uint32_t so1 = swz64(r1f * 64 + q1f * 16);
        const long gA0 = (long)(m0 + r0f) * 256 + c * KC_ + q0f * 8;
        const long gA1 = (long)(m0 + r1f) * 256 + c * KC_ + q1f * 8;
        const long gB0 = (long)(n0 + r0f) * 256 + c * KC_ + q0f * 8;
        const long gB1 = (long)(n0 + r1f) * 256 + c * KC_ + q1f * 8;
        cpa16(st +          so0, Ah + gA0);
        cpa16(st +          so1, Ah + gA1);
        cpa16(st +  8192u + so0, Al + gA0);
        cpa16(st +  8192u + so1, Al + gA1);
        cpa16(st + 16384u + so0, Bh + gB0);
        cpa16(st + 16384u + so1, Bh + gB1);
        cpa16(st + 24576u + so0, Bl + gB0);
        cpa16(st + 24576u + so1, Bl + gB1);
    };

    load_stage(0, 0);
    asm volatile("cp.async.commit_group;" ::: "memory");

    for (int c = 0; c < NCH_; c++) {
        if (c + 1 < NCH_) {
            load_stage(c + 1, (c + 1) & 1);
            asm volatile("cp.async.commit_group;" ::: "memory");
            asm volatile("cp.async.wait_group 1;" ::: "memory");
        } else {
            asm volatile("cp.async.wait_group 0;" ::: "memory");
        }
        __syncthreads();

        const uint32_t st = sbase + (uint32_t)(c & 1) * STGB_;
        const uint32_t uAh = st, uAl = st + 8192u;
        const uint32_t uBh = st + 16384u, uBl = st + 24576u;

        #pragma unroll
        for (int ks = 0; ks < 2; ks++) {
            uint32_t bh[2][4], bl[2][4];
            #pragma unroll
            for (int ng = 0; ng < 2; ng++) {
                uint32_t boff = swz64((uint32_t)(wn * 32 + ng * 16 + bN) * 64
                                      + ks * 32 + bK8 * 16);
                ldm4(bh[ng], uBh + boff);
                ldm4(bl[ng], uBl + boff);
            }
            #pragma unroll
            for (int mt = 0; mt < 4; mt++) {
                uint32_t ah[4], al[4];
                uint32_t aoff = swz64((uint32_t)(wm * 64 + mt * 16 + aR) * 64
                                      + ks * 32 + aC16 * 16);
                ldm4(ah, uAh + aoff);
                ldm4(al, uAl + aoff);
                #pragma unroll
                for (int nt = 0; nt < 4; nt++) {
                    const int ng = nt >> 1, sb = (nt & 1) * 2;
                    mma16816(acc[mt][nt], ah, bh[ng][sb], bh[ng][sb + 1]);
                    mma16816(acc[mt][nt], ah, bl[ng][sb], bl[ng][sb + 1]);
                    mma16816(acc[mt][nt], al, bh[ng][sb], bh[ng][sb + 1]);
                }
            }
        }
        __syncthreads();
    }

    // ---- epilogue ----
    const int er = lane >> 2;
    const int ec = (lane & 3) * 2;
    #pragma unroll
    for (int mt = 0; mt < 4; mt++) {
        #pragma unroll
        for (int nt = 0; nt < 4; nt++) {
            const long m = m0 + wm * 64 + mt * 16 + er;
            const int  n = n0 + wn * 32 + nt * 8 + ec;
            float bx = bias[n], by = bias[n + 1];
            float2 o0, o1;
            o0.x = acc[mt][nt][0] + bx; o0.y = acc[mt][nt][1] + by;
            o1.x = acc[mt][nt][2] + bx; o1.y = acc[mt][nt][3] + by;
            if (res) {
                float2 r0 = *(const float2*)(res + m * ldr + n);
                float2 r1 = *(const float2*)(res + (m + 8) * ldr + n);
                o0.x += r0.x; o0.y += r0.y;
                o1.x += r1.x; o1.y += r1.y;
            }
            *(float2*)(C + m * ldc + n) = o0;
            *(float2*)(C + (m + 8) * ldc + n) = o1;
        }
    }
}

// ------------------------- fp32 -> bf16 hi/lo split -------------------------
__global__ void __launch_bounds__(256) split_a(
    const float* __restrict__ a,
    __nv_bfloat16* __restrict__ h, __nv_bfloat16* __restrict__ l)
{
    int i = blockIdx.x * 256 + threadIdx.x;     // float4 index
    float4 v = ((const float4*)a)[i];
    __nv_bfloat16 hx = __float2bfloat16(v.x);
    __nv_bfloat16 hy = __float2bfloat16(v.y);
    __nv_bfloat16 hz = __float2bfloat16(v.z);
    __nv_bfloat16 hw = __float2bfloat16(v.w);
    __nv_bfloat162* hp = (__nv_bfloat162*)(h + i * 4);
    __nv_bfloat162* lp = (__nv_bfloat162*)(l + i * 4);
    __nv_bfloat162 h0; h0.x = hx; h0.y = hy;
    __nv_bfloat162 h1; h1.x = hz; h1.y = hw;
    __nv_bfloat162 l0, l1;
    l0.x = __float2bfloat16(v.x - __bfloat162float(hx));
    l0.y = __float2bfloat16(v.y - __bfloat162float(hy));
    l1.x = __float2bfloat16(v.z - __bfloat162float(hz));
    l1.y = __float2bfloat16(v.w - __bfloat162float(hw));
    hp[0] = h0; hp[1] = h1;
    lp[0] = l0; lp[1] = l1;
}

// ------------------------- weight/bias packing ------------------------------
__global__ void __launch_bounds__(256) pack_w(
    const float* __restrict__ Wq, const float* __restrict__ Wk, const float* __restrict__ Wv,
    const float* __restrict__ bq, const float* __restrict__ bk, const float* __restrict__ bv,
    float* __restrict__ Wp, float* __restrict__ bp)
{
    int idx = blockIdx.x * 256 + threadIdx.x;
    int k = idx / 768, c = idx % 768;
    int sel = c >> 8, cc = c & 255;
    const float* W = (sel == 0) ? Wq : (sel == 1) ? Wk : Wv;
    Wp[idx] = W[k * 256 + cc];
    if (idx < 768) {
        const float* b = (sel == 0) ? bq : (sel == 1) ? bk : bv;
        bp[idx] = b[cc];
    }
}

__global__ void __launch_bounds__(256) pack_wt(
    const float* __restrict__ W0, const float* __restrict__ W1, const float* __restrict__ W2,
    __nv_bfloat16* __restrict__ th, __nv_bfloat16* __restrict__ tl)
{
    int idx = blockIdx.x * 256 + threadIdx.x;
    int n = idx >> 8, k = idx & 255;
    int sel = n >> 8, nc = n & 255;
    const float* W = (sel == 0) ? W0 : (sel == 1) ? W1 : W2;
    float v = W[k * 256 + nc];
    __nv_bfloat16 h = __float2bfloat16(v);
    th[idx] = h;
    tl[idx] = __float2bfloat16(v - __bfloat162float(h));
}

// ------------------------------ mean over L ---------------------------------
__global__ void __launch_bounds__(256) mean_stage1(const float* __restrict__ x,
                                                   float* __restrict__ part)
{
    int s = blockIdx.x, n = blockIdx.y, c = threadIdx.x;
    const float* base = x + ((long)n * L_ + (long)s * 128) * H_ + c;
    float sum = 0.f;
    #pragma unroll 8
    for (int l = 0; l < 128; l++) sum += base[(long)l * H_];
    part[(n * 32 + s) * H_ + c] = sum;
}

__global__ void __launch_bounds__(256) mean_stage2(const float* __restrict__ part,
                                                   float* __restrict__ center)
{
    int n = blockIdx.x, c = threadIdx.x;
    float sum = 0.f;
    #pragma unroll
    for (int s = 0; s < 32; s++) sum += part[(n * 32 + s) * H_ + c];
    center[n * H_ + c] = sum * (1.f / (float)L_);
}

// ---------------------- tiny projection: center @ Wpack ---------------------
__global__ void __launch_bounds__(256) cen_proj(
    const float* __restrict__ center, const float* __restrict__ Wp,
    const float* __restrict__ bp, float* __restrict__ out)
{
    __shared__ float sh[256];
    int idx = blockIdx.x * 256 + threadIdx.x;
    int r = idx / 768, c = idx % 768;
    sh[threadIdx.x] = center[r * 256 + threadIdx.x];
    __syncthreads();
    float s = bp[c];
    #pragma unroll 8
    for (int k = 0; k < 256; k++) s += sh[k] * Wp[k * 768 + c];
    out[idx] = s;
}

// --------------------------- sat attention ----------------------------------
// Outputs ctx directly as bf16 hi/lo (feeds the Wo GEMM).
__global__ void __launch_bounds__(256) sat_attn(
    const float* __restrict__ qkv,    // [NPOS,768]
    const float* __restrict__ kvx,    // [NPOS,512]
    const float* __restrict__ cen,    // [B,768]
    __nv_bfloat16* __restrict__ ctxH,
    __nv_bfloat16* __restrict__ ctxL)
{
    int warp = (blockIdx.x * blockDim.x + threadIdx.x) >> 5;
    int lane = threadIdx.x & 31;
    if (warp >= NPOS) return;
    int n = warp >> 12;
    int l = warp & (L_ - 1);
    long i  = warp;
    long rb = (long)n * L_ + ((l + 1 == L_) ? 0 : l + 1);
    long ra = (long)n * L_ + ((l == 0) ? (L_ - 1) : 0);

    #pragma unroll
    for (int h = 0; h < 8; h++) {
        int off = h * 32 + lane;
        float qv = qkv[i * 768 + off];
        float k0 = qkv[rb * 768 + 256 + off];
        float k1 = qkv[i  * 768 + 256 + off];
        float k2 = qkv[ra * 768 + 256 + off];
        float k3 = kvx[i * 512 + off];
        float k4 = cen[n * 768 + 256 + off];
        float s0 = wsum(qv * k0) * SCALE_;
        float s1 = wsum(qv * k1) * SCALE_;
        float s2 = wsum(qv * k2) * SCALE_;
        float s3 = wsum(qv * k3) * SCALE_;
        float s4 = wsum(qv * k4) * SCALE_;
        float m = fmaxf(fmaxf(fmaxf(s0, s1), fmaxf(s2, s3)), s4);
        float p0 = __expf(s0 - m), p1 = __expf(s1 - m), p2 = __expf(s2 - m);
        float p3 = __expf(s3 - m), p4 = __expf(s4 - m);
        float den = p0 + p1 + p2 + p3 + p4;
        float v0 = qkv[rb * 768 + 512 + off];
        float v1 = qkv[i  * 768 + 512 + off];
        float v2 = qkv[ra * 768 + 512 + off];
        float v3 = kvx[i * 512 + 256 + off];
        float v4 = cen[n * 768 + 512 + off];
        float o = (p0 * v0 + p1 * v1 + p2 * v2 + p3 * v3 + p4 * v4) / den;
        __nv_bfloat16 hh = __float2bfloat16(o);
        ctxH[i * 256 + off] = hh;
        ctxL[i * 256 + off] = __float2bfloat16(o - __bfloat162float(hh));
    }
}

// ---------------- relu + layernorm (also emits bf16 hi/lo) ------------------
__global__ void __launch_bounds__(256) relu_ln(
    const float* __restrict__ in, const float* __restrict__ w,
    const float* __restrict__ b, float* __restrict__ out,
    __nv_bfloat16* __restrict__ outH, __nv_bfloat16* __restrict__ outL)
{
    long row = blockIdx.x;
    int c = threadIdx.x;
    float v = fmaxf(in[row * 256 + c], 0.f);
    __shared__ float sh[16];
    int lane = c & 31, wid = c >> 5;
    float rs = wsum(v), rq = wsum(v * v);
    if (lane == 0) { sh[wid] = rs; sh[8 + wid] = rq; }
    __syncthreads();
    float ts = 0.f, tq = 0.f;
    #pragma unroll
    for (int i = 0; i < 8; i++) { ts += sh[i]; tq += sh[8 + i]; }
    float u = ts * (1.f / 256.f);
    float var = tq * (1.f / 256.f) - u * u;
    float o = w[c] * (v - u) * rsqrtf(var + 1e-12f) + b[c];
    out[row * 256 + c] = o;
    __nv_bfloat16 hh = __float2bfloat16(o);
    outH[row * 256 + c] = hh;
    outL[row * 256 + c] = __float2bfloat16(o - __bfloat162float(hh));
}

// --------------------------- rel attention ----------------------------------
__global__ void __launch_bounds__(256) rel_attn(
    const float* __restrict__ cen,   // [B,768]
    const float* __restrict__ kvr,   // [NPOS,512]
    float* __restrict__ rctx)        // [B,256]
{
    int n = blockIdx.x >> 3, h = blockIdx.x & 7;
    int w = threadIdx.x >> 5, lane = threadIdx.x & 31;
    int off = h * 32 + lane;
    float qv = cen[n * 768 + off];
    float m = -1e30f, s = 0.f, acc = 0.f;
    for (int t = w; t <= L_; t += 8) {
        float kv, vv;
        if (t == 0) { kv = cen[n * 768 + 256 + off]; vv = cen[n * 768 + 512 + off]; }
        else {
            long r = (long)n * L_ + (t - 1);
            kv = kvr[r * 512 + off];
            vv = kvr[r * 512 + 256 + off];
        }
        float d = wsum(qv * kv) * SCALE_;
        float mn = fmaxf(m, d);
        float eo = __expf(m - mn);
        float en = __expf(d - mn);
        s = s * eo + en;
        acc = acc * eo + en * vv;
        m = mn;
    }
    __shared__ float sm[8], ss[8], sacc[8][32];
    sacc[w][lane] = acc;
    if (lane == 0) { sm[w] = m; ss[w] = s; }
    __syncthreads();
    if (w == 0) {
        float M = sm[0];
        #pragma unroll
        for (int r = 1; r < 8; r++) M = fmaxf(M, sm[r]);
        float S = 0.f, A = 0.f;
        #pragma unroll
        for (int r = 0; r < 8; r++) {
            float f = __expf(sm[r] - M);
            S += ss[r] * f;
            A += sacc[r][lane] * f;
        }
        rctx[n * 256 + off] = A / S;
    }
}

// ---------------- rel output: rctx@Wo + bo + center, relu, LN ---------------
__global__ void __launch_bounds__(256) rel_out(
    const float* __restrict__ rctx, const float* __restrict__ Wo,
    const float* __restrict__ bo, float* __restrict__ center,
    const float* __restrict__ lnw, const float* __restrict__ lnb)
{
    int n = blockIdx.x, c = threadIdx.x;
    __shared__ float sa[256];
    sa[c] = rctx[n * 256 + c];
    __syncthreads();
    float o = bo[c] + center[n * 256 + c];
    #pragma unroll 8
    for (int k = 0; k < 256; k++) o += sa[k] * Wo[k * 256 + c];
    o = fmaxf(o, 0.f);
    __shared__ float sh[16];
    int lane = c & 31, wid = c >> 5;
    float rs = wsum(o), rq = wsum(o * o);
    if (lane == 0) { sh[wid] = rs; sh[8 + wid] = rq; }
    __syncthreads();
    float ts = 0.f, tq = 0.f;
    #pragma unroll
    for (int i = 0; i < 8; i++) { ts += sh[i]; tq += sh[8 + i]; }
    float u = ts * (1.f / 256.f);
    float var = tq * (1.f / 256.f) - u * u;
    center[n * 256 + c] = lnw[c] * (o - u) * rsqrtf(var + 1e-12f) + lnb[c];
}

// ------------------------------- output copy --------------------------------
__global__ void write_out(const float* __restrict__ cur, const float* __restrict__ center,
                          float* __restrict__ out, int ncur, int ntot)
{
    for (int i = blockIdx.x * blockDim.x + threadIdx.x; i < ntot; i += gridDim.x * blockDim.x) {
        if (i < ncur) out[i] = cur[i];
        else {
            int j = i - ncur;
            out[i] = (j < B_ * H_) ? center[j] : 0.f;
        }
    }
}

// ------------------------------- host side ----------------------------------
extern "C" void kernel_launch(void* const* d_in, const int* in_sizes, int n_in,
                              void* d_out, int out_size)
{
    const float* x    = (const float*)d_in[0];
    const float* sWq  = (const float*)d_in[1];
    const float* sbq  = (const float*)d_in[2];
    const float* sWk  = (const float*)d_in[3];
    const float* sbk  = (const float*)d_in[4];
    const float* sWv  = (const float*)d_in[5];
    const float* sbv  = (const float*)d_in[6];
    const float* sWo  = (const float*)d_in[7];
    const float* sbo  = (const float*)d_in[8];
    const float* rWq  = (const float*)d_in[9];
    const float* rbq  = (const float*)d_in[10];
    const float* rWk  = (const float*)d_in[11];
    const float* rbk  = (const float*)d_in[12];
    const float* rWv  = (const float*)d_in[13];
    const float* rbv  = (const float*)d_in[14];
    const float* rWo  = (const float*)d_in[15];
    const float* rbo  = (const float*)d_in[16];
    const float* slnw = (const float*)d_in[17];
    const float* slnb = (const float*)d_in[18];
    const float* rlnw = (const float*)d_in[19];
    const float* rlnb = (const float*)d_in[20];

    float *QKVc, *KVx, *KVr, *satpre, *cur, *center, *part;
    float *cenSat, *cenRel, *rctx, *satW, *relW, *satB, *relB;
    __nv_bfloat16 *xH, *xL, *ctxH, *ctxL, *curH, *curL;
    __nv_bfloat16 *sWtH, *sWtL, *rWtH, *rWtL, *sWoTH, *sWoTL;
    cudaGetSymbolAddress((void**)&QKVc,   g_QKVc);
    cudaGetSymbolAddress((void**)&KVx,    g_KVx);
    cudaGetSymbolAddress((void**)&KVr,    g_KVr);
    cudaGetSymbolAddress((void**)&satpre, g_satpre);
    cudaGetSymbolAddress((void**)&cur,    g_cur);
    cudaGetSymbolAddress((void**)&center, g_center);
    cudaGetSymbolAddress((void**)&part,   g_part);
    cudaGetSymbolAddress((void**)&cenSat, g_cenSat);
    cudaGetSymbolAddress((void**)&cenRel, g_cenRel);
    cudaGetSymbolAddress((void**)&rctx,   g_rctx);
    cudaGetSymbolAddress((void**)&satW,   g_satW);
    cudaGetSymbolAddress((void**)&relW,   g_relW);
    cudaGetSymbolAddress((void**)&satB,   g_satBias);
    cudaGetSymbolAddress((void**)&relB,   g_relBias);
    cudaGetSymbolAddress((void**)&xH,     g_xH);
    cudaGetSymbolAddress((void**)&xL,     g_xL);
    cudaGetSymbolAddress((void**)&ctxH,   g_ctxH);
    cudaGetSymbolAddress((void**)&ctxL,   g_ctxL);
    cudaGetSymbolAddress((void**)&curH,   g_curH);
    cudaGetSymbolAddress((void**)&curL,   g_curL);
    cudaGetSymbolAddress((void**)&sWtH,   g_sWtH);
    cudaGetSymbolAddress((void**)&sWtL,   g_sWtL);
    cudaGetSymbolAddress((void**)&rWtH,   g_rWtH);
    cudaGetSymbolAddress((void**)&rWtL,   g_rWtL);
    cudaGetSymbolAddress((void**)&sWoTH,  g_sWoTH);
    cudaGetSymbolAddress((void**)&sWoTL,  g_sWoTL);

    cudaFuncSetAttribute(gemm_mma, cudaFuncAttributeMaxDynamicSharedMemorySize, GSMEM_DYN);

    // packs + input split
    pack_w<<<768, 256>>>(sWq, sWk, sWv, sbq, sbk, sbv, satW, satB);
    pack_w<<<768, 256>>>(rWq, rWk, rWv, rbq, rbk, rbv, relW, relB);
    pack_wt<<<768, 256>>>(sWq, sWk, sWv, sWtH, sWtL);
    pack_wt<<<768, 256>>>(rWq, rWk, rWv, rWtH, rWtL);
    pack_wt<<<256, 256>>>(sWo, sWo, sWo, sWoTH, sWoTL);
    split_a<<<NPOS * 256 / 1024, 256>>>(x, xH, xL);

    // center0 = mean_L(x)
    mean_stage1<<<dim3(32, B_), 256>>>(x, part);
    mean_stage2<<<B_, 256>>>(part, center);

    // K/V of x (once)
    gemm_mma<<<dim3(4, NPOS / 128), 256, GSMEM_DYN>>>(
        xH, xL, sWtH + 256 * 256, sWtL + 256 * 256, satB + 256, nullptr, 0, KVx, 512);

    for (int it = 0; it < 2; it++) {
        const __nv_bfloat16* aH = (it == 0) ? xH : curH;
        const __nv_bfloat16* aL = (it == 0) ? xL : curL;
        const float* resf = (it == 0) ? x : cur;

        cen_proj<<<24, 256>>>(center, satW, satB, cenSat);
        gemm_mma<<<dim3(6, NPOS / 128), 256, GSMEM_DYN>>>(
            aH, aL, sWtH, sWtL, satB, nullptr, 0, QKVc, 768);
        sat_attn<<<NPOS / 8, 256>>>(QKVc, KVx, cenSat, ctxH, ctxL);
        gemm_mma<<<dim3(2, NPOS / 128), 256, GSMEM_DYN>>>(
            ctxH, ctxL, sWoTH, sWoTL, sbo, resf, 256, satpre, 256);
        relu_ln<<<NPOS, 256>>>(satpre, slnw, slnb, cur, curH, curL);

        cen_proj<<<24, 256>>>(center, relW, relB, cenRel);
        gemm_mma<<<dim3(4, NPOS / 128), 256, GSMEM_DYN>>>(
            curH, curL, rWtH + 256 * 256, rWtL + 256 * 256, relB + 256, nullptr, 0, KVr, 512);
        rel_attn<<<B_ * 8, 256>>>(cenRel, KVr, rctx);
        rel_out<<<B_, 256>>>(rctx, rWo, rbo, center, rlnw, rlnb);
    }

    write_out<<<2048, 256>>>(cur, center, (float*)d_out, NPOS * H_, out_size);
}

// round 11
// speedup vs baseline: 1.9200x; 1.1002x over previous
#include <cuda_runtime.h>
#include <cuda_bf16.h>
#include <cuda_fp16.h>
#include <cstdint>

// ---------------------------------------------------------------------------
// StarTransformerLayer  B=8 L=4096 H=256 NH=8 HD=32, 2 iterations.
// Round 9: fp16 2-product GEMM (A split fp16 hi/lo, weights single fp16),
// with the pack_w2 bitmask bug fixed (768 is not a power of two -> use
// division / explicit compares).  cp.async 2-stage pipeline, SW64 swizzle.
// ---------------------------------------------------------------------------

#define B_   8
#define L_   4096
#define H_   256
#define NPOS (B_*L_)              // 32768
#define SCALE_ 0.17677669529663689f   // 1/sqrt(32)

// ------------------------- scratch (device globals) ------------------------
__device__ float g_QKVc [NPOS*768];
__device__ float g_KVx  [NPOS*512];
__device__ float g_KVr  [NPOS*512];
__device__ float g_satpre[NPOS*256];
__device__ float g_cur  [NPOS*256];
__device__ float g_center[B_*H_];
__device__ float g_part [B_*32*H_];
__device__ float g_cenSat[B_*768];
__device__ float g_cenRel[B_*768];
__device__ float g_rctx [B_*H_];
__device__ float g_satW [256*768];
__device__ float g_relW [256*768];
__device__ float g_satBias[768];
__device__ float g_relBias[768];
// pre-split fp16 hi/lo activations (GEMM A operands)
__device__ __half g_xH  [NPOS*256];
__device__ __half g_xL  [NPOS*256];
__device__ __half g_ctxH[NPOS*256];
__device__ __half g_ctxL[NPOS*256];
__device__ __half g_curH[NPOS*256];
__device__ __half g_curL[NPOS*256];
// transposed weights: [N,256] K-major fp16
__device__ __half g_sWt [768*256];
__device__ __half g_rWt [768*256];
__device__ __half g_sWoT[256*256];

// ------------------------------ helpers -------------------------------------
__device__ __forceinline__ uint32_t su32(const void* p) {
    return (uint32_t)__cvta_generic_to_shared(p);
}
__device__ __forceinline__ uint32_t swz64(uint32_t o) {   // 64B-row swizzle
    return o ^ ((o >> 3) & 0x30);
}
__device__ __forceinline__ void cpa16(uint32_t saddr, const void* g) {
    asm volatile("cp.async.cg.shared.global [%0], [%1], 16;"
                 :: "r"(saddr), "l"(g));
}
__device__ __forceinline__ void ldm4(uint32_t* r, uint32_t addr) {
    asm volatile("ldmatrix.sync.aligned.m8n8.x4.shared.b16 {%0,%1,%2,%3}, [%4];"
                 : "=r"(r[0]), "=r"(r[1]), "=r"(r[2]), "=r"(r[3]) : "r"(addr));
}
__device__ __forceinline__ void mma16816h(float* d, const uint32_t* a,
                                          uint32_t b0, uint32_t b1) {
    asm volatile(
        "mma.sync.aligned.m16n8k16.row.col.f32.f16.f16.f32 "
        "{%0,%1,%2,%3}, {%4,%5,%6,%7}, {%8,%9}, {%0,%1,%2,%3};"
        : "+f"(d[0]), "+f"(d[1]), "+f"(d[2]), "+f"(d[3])
        : "r"(a[0]), "r"(a[1]), "r"(a[2]), "r"(a[3]), "r"(b0), "r"(b1));
}
__device__ __forceinline__ float wsum(float v) {
    v += __shfl_xor_sync(0xffffffffu, v, 16);
    v += __shfl_xor_sync(0xffffffffu, v, 8);
    v += __shfl_xor_sync(0xffffffffu, v, 4);
    v += __shfl_xor_sync(0xffffffffu, v, 2);
    v += __shfl_xor_sync(0xffffffffu, v, 1);
    return v;
}

// =========================== HMMA GEMM ======================================
// C[M,N] = (Ah+Al)[M,256] @ B^T + bias (+ res fp32).   B fp16 [N,256].
// Tile 128x128.  K chunks of 32, 2-stage cp.async pipeline.  2 CTA/SM.
#define KC_    32
#define NCH_   8
#define STGB_  24576           // 3 arrays x 8KB per stage
#define GSMEM_DYN (2*STGB_ + 1024)

__global__ void __launch_bounds__(256, 2) gemm_mma(
    const __half* __restrict__ Ah,   // [M,256]
    const __half* __restrict__ Al,
    const __half* __restrict__ Bt,   // [N,256] K-major
    const float* __restrict__ bias,
    const float* __restrict__ res, int ldr,
    float* __restrict__ C, int ldc)
{
    extern __shared__ char smem_raw[];
    char* smem = (char*)(((uintptr_t)smem_raw + 1023) & ~(uintptr_t)1023);
    const uint32_t sbase = su32(smem);

    const int tid  = threadIdx.x;
    const int wid  = tid >> 5;
    const int lane = tid & 31;
    const int wm = wid >> 2;        // 0..1
    const int wn = wid & 3;         // 0..3
    const int m0 = blockIdx.y * 128;
    const int n0 = blockIdx.x * 128;

    // fill indexing: 512 16B-chunks per 8KB array, 2 per thread
    const int r0f = tid >> 2,         q0f = tid & 3;
    const int r1f = (tid + 256) >> 2, q1f = (tid + 256) & 3;

    float acc[4][4][4];
    #pragma unroll
    for (int i = 0; i < 4; i++)
        #pragma unroll
        for (int j = 0; j < 4; j++)
            #pragma unroll
            for (int t = 0; t < 4; t++) acc[i][j][t] = 0.f;

    const int aR = lane & 15;
    const int aC16 = lane >> 4;
    const int bN = (lane & 7) + ((lane >> 1) & 8);
    const int bK8 = (lane >> 3) & 1;

    auto load_stage = [&](int c, int s) {
        uint32_t st = sbase + (uint32_t)s * STGB_;
        const uint32_t so0 = swz64(r0f * 64 + q0f * 16);
        const uint32_t so1 = swz64(r1f * 64 + q1f * 16);
        const long gA0 = (long)(m0 + r0f) * 256 + c * KC_ + q0f * 8;
        const long gA1 = (long)(m0 + r1f) * 256 + c * KC_ + q1f * 8;
        const long gB0 = (long)(n0 + r0f) * 256 + c * KC_ + q0f * 8;
        const long gB1 = (long)(n0 + r1f) * 256 + c * KC_ + q1f * 8;
        cpa16(st +          so0, Ah + gA0);
        cpa16(st +          so1, Ah + gA1);
        cpa16(st +  8192u + so0, Al + gA0);
        cpa16(st +  8192u + so1, Al + gA1);
        cpa16(st + 16384u + so0, Bt + gB0);
        cpa16(st + 16384u + so1, Bt + gB1);
    };

    load_stage(0, 0);
    asm volatile("cp.async.commit_group;" ::: "memory");

    for (int c = 0; c < NCH_; c++) {
        if (c + 1 < NCH_) {
            load_stage(c + 1, (c + 1) & 1);
            asm volatile("cp.async.commit_group;" ::: "memory");
            asm volatile("cp.async.wait_group 1;" ::: "memory");
        } else {
            asm volatile("cp.async.wait_group 0;" ::: "memory");
        }
        __syncthreads();

        const uint32_t st = sbase + (uint32_t)(c & 1) * STGB_;
        const uint32_t uAh = st, uAl = st + 8192u, uBt = st + 16384u;

        #pragma unroll
        for (int ks = 0; ks < 2; ks++) {
            uint32_t bf[2][4];
            #pragma unroll
            for (int ng = 0; ng < 2; ng++) {
                uint32_t boff = swz64((uint32_t)(wn * 32 + ng * 16 + bN) * 64
                                      + ks * 32 + bK8 * 16);
                ldm4(bf[ng], uBt + boff);
            }
            #pragma unroll
            for (int mt = 0; mt < 4; mt++) {
                uint32_t ah[4], al[4];
                uint32_t aoff = swz64((uint32_t)(wm * 64 + mt * 16 + aR) * 64
                                      + ks * 32 + aC16 * 16);
                ldm4(ah, uAh + aoff);
                ldm4(al, uAl + aoff);
                #pragma unroll
                for (int nt = 0; nt < 4; nt++) {
                    const int ng = nt >> 1, sb = (nt & 1) * 2;
                    mma16816h(acc[mt][nt], ah, bf[ng][sb], bf[ng][sb + 1]);
                    mma16816h(acc[mt][nt], al, bf[ng][sb], bf[ng][sb + 1]);
                }
            }
        }
        __syncthreads();
    }

    // ---- epilogue ----
    const int er = lane >> 2;
    const int ec = (lane & 3) * 2;
    #pragma unroll
    for (int mt = 0; mt < 4; mt++) {
        #pragma unroll
        for (int nt = 0; nt < 4; nt++) {
            const long m = m0 + wm * 64 + mt * 16 + er;
            const int  n = n0 + wn * 32 + nt * 8 + ec;
            float bx = bias[n], by = bias[n + 1];
            float2 o0, o1;
            o0.x = acc[mt][nt][0] + bx; o0.y = acc[mt][nt][1] + by;
            o1.x = acc[mt][nt][2] + bx; o1.y = acc[mt][nt][3] + by;
            if (res) {
                float2 r0 = *(const float2*)(res + m * ldr + n);
                float2 r1 = *(const float2*)(res + (m + 8) * ldr + n);
                o0.x += r0.x; o0.y += r0.y;
                o1.x += r1.x; o1.y += r1.y;
            }
            *(float2*)(C + m * ldc + n) = o0;
            *(float2*)(C + (m + 8) * ldc + n) = o1;
        }
    }
}

// ------------------------- fp32 -> fp16 hi/lo split -------------------------
__global__ void __launch_bounds__(256) split_a(
    const float* __restrict__ a,
    __half* __restrict__ h, __half* __restrict__ l)
{
    int i = blockIdx.x * 256 + threadIdx.x;     // float4 index
    float4 v = ((const float4*)a)[i];
    __half hx = __float2half_rn(v.x);
    __half hy = __float2half_rn(v.y);
    __half hz = __float2half_rn(v.z);
    __half hw = __float2half_rn(v.w);
    __half2* hp = (__half2*)(h + i * 4);
    __half2* lp = (__half2*)(l + i * 4);
    __half2 h0; h0.x = hx; h0.y = hy;
    __half2 h1; h1.x = hz; h1.y = hw;
    __half2 l0, l1;
    l0.x = __float2half_rn(v.x - __half2float(hx));
    l0.y = __float2half_rn(v.y - __half2float(hy));
    l1.x = __float2half_rn(v.z - __half2float(hz));
    l1.y = __float2half_rn(v.w - __half2float(hw));
    hp[0] = h0; hp[1] = h1;
    lp[0] = l0; lp[1] = l1;
}

// ------------------------- weight/bias packing ------------------------------
// fp32 pack for cen_proj (correct div/mod arithmetic — R3..R7 proven)
__global__ void __launch_bounds__(256) pack_w(
    const float* __restrict__ Wq, const float* __restrict__ Wk, const float* __restrict__ Wv,
    const float* __restrict__ bq, const float* __restrict__ bk, const float* __restrict__ bv,
    float* __restrict__ Wp, float* __restrict__ bp)
{
    int idx = blockIdx.x * 256 + threadIdx.x;
    int k = idx / 768, c = idx % 768;
    int sel = c >> 8, cc = c & 255;
    const float* W = (sel == 0) ? Wq : (sel == 1) ? Wk : Wv;
    Wp[idx] = W[k * 256 + cc];
    if (idx < 768) {
        const float* b = (sel == 0) ? bq : (sel == 1) ? bk : bv;
        bp[idx] = b[cc];
    }
}

// all fp16 transposed weight packs in ONE launch (explicit range compares)
__global__ void __launch_bounds__(256) pack_wt_all(
    const float* __restrict__ sWq, const float* __restrict__ sWk, const float* __restrict__ sWv,
    const float* __restrict__ rWq, const float* __restrict__ rWk, const float* __restrict__ rWv,
    const float* __restrict__ sWo,
    __half* __restrict__ sWt, __half* __restrict__ rWt, __half* __restrict__ sWoT)
{
    int blk = blockIdx.x;                 // 0..1791
    if (blk < 768) {
        int idx = blk * 256 + threadIdx.x;
        int n = idx >> 8, k = idx & 255;
        int sel = n >> 8, nc = n & 255;
        const float* W = (sel == 0) ? sWq : (sel == 1) ? sWk : sWv;
        sWt[idx] = __float2half_rn(W[k * 256 + nc]);
    } else if (blk < 1536) {
        int idx = (blk - 768) * 256 + threadIdx.x;
        int n = idx >> 8, k = idx & 255;
        int sel = n >> 8, nc = n & 255;
        const float* W = (sel == 0) ? rWq : (sel == 1) ? rWk : rWv;
        rWt[idx] = __float2half_rn(W[k * 256 + nc]);
    } else {
        int idx = (blk - 1536) * 256 + threadIdx.x;
        int n = idx >> 8, k = idx & 255;       // n < 256
        sWoT[idx] = __float2half_rn(sWo[k * 256 + n]);
    }
}

// ------------------------------ mean over L ---------------------------------
__global__ void __launch_bounds__(256) mean_stage1(const float* __restrict__ x,
                                                   float* __restrict__ part)
{
    int s = blockIdx.x, n = blockIdx.y, c = threadIdx.x;
    const float* base = x + ((long)n * L_ + (long)s * 128) * H_ + c;
    float sum = 0.f;
    #pragma unroll 8
    for (int l = 0; l < 128; l++) sum += base[(long)l * H_];
    part[(n * 32 + s) * H_ + c] = sum;
}

__global__ void __launch_bounds__(256) mean_stage2(const float* __restrict__ part,
                                                   float* __restrict__ center)
{
    int n = blockIdx.x, c = threadIdx.x;
    float sum = 0.f;
    #pragma unroll
    for (int s = 0; s < 32; s++) sum += part[(n * 32 + s) * H_ + c];
    center[n * H_ + c] = sum * (1.f / (float)L_);
}

// ---------------------- tiny projection: center @ Wpack ---------------------
__global__ void __launch_bounds__(256) cen_proj(
    const float* __restrict__ center, const float* __restrict__ Wp,
    const float* __restrict__ bp, float* __restrict__ out)
{
    __shared__ float sh[256];
    int idx = blockIdx.x * 256 + threadIdx.x;
    int r = idx / 768, c = idx % 768;
    sh[threadIdx.x] = center[r * 256 + threadIdx.x];
    __syncthreads();
    float s = bp[c];
    #pragma unroll 8
    for (int k = 0; k < 256; k++) s += sh[k] * Wp[k * 768 + c];
    out[idx] = s;
}

// --------------------------- sat attention ----------------------------------
__global__ void __launch_bounds__(256) sat_attn(
    const float* __restrict__ qkv,    // [NPOS,768]
    const float* __restrict__ kvx,    // [NPOS,512]
    const float* __restrict__ cen,    // [B,768]
    __half* __restrict__ ctxH,
    __half* __restrict__ ctxL)
{
    int warp = (blockIdx.x * blockDim.x + threadIdx.x) >> 5;
    int lane = threadIdx.x & 31;
    if (warp >= NPOS) return;
    int n = warp >> 12;
    int l = warp & (L_ - 1);
    long i  = warp;
    long rb = (long)n * L_ + ((l + 1 == L_) ? 0 : l + 1);
    long ra = (long)n * L_ + ((l == 0) ? (L_ - 1) : 0);

    #pragma unroll
    for (int h = 0; h < 8; h++) {
        int off = h * 32 + lane;
        float qv = qkv[i * 768 + off];
        float k0 = qkv[rb * 768 + 256 + off];
        float k1 = qkv[i  * 768 + 256 + off];
        float k2 = qkv[ra * 768 + 256 + off];
        float k3 = kvx[i * 512 + off];
        float k4 = cen[n * 768 + 256 + off];
        float s0 = wsum(qv * k0) * SCALE_;
        float s1 = wsum(qv * k1) * SCALE_;
        float s2 = wsum(qv * k2) * SCALE_;
        float s3 = wsum(qv * k3) * SCALE_;
        float s4 = wsum(qv * k4) * SCALE_;
        float m = fmaxf(fmaxf(fmaxf(s0, s1), fmaxf(s2, s3)), s4);
        float p0 = __expf(s0 - m), p1 = __expf(s1 - m), p2 = __expf(s2 - m);
        float p3 = __expf(s3 - m), p4 = __expf(s4 - m);
        float den = p0 + p1 + p2 + p3 + p4;
        float v0 = qkv[rb * 768 + 512 + off];
        float v1 = qkv[i  * 768 + 512 + off];
        float v2 = qkv[ra * 768 + 512 + off];
        float v3 = kvx[i * 512 + 256 + off];
        float v4 = cen[n * 768 + 512 + off];
        float o = (p0 * v0 + p1 * v1 + p2 * v2 + p3 * v3 + p4 * v4) / den;
        __half hh = __float2half_rn(o);
        ctxH[i * 256 + off] = hh;
        ctxL[i * 256 + off] = __float2half_rn(o - __half2float(hh));
    }
}

// ---------------- relu + layernorm (also emits fp16 hi/lo) ------------------
__global__ void __launch_bounds__(256) relu_ln(
    const float* __restrict__ in, const float* __restrict__ w,
    const float* __restrict__ b, float* __restrict__ out,
    __half* __restrict__ outH, __half* __restrict__ outL)
{
    long row = blockIdx.x;
    int c = threadIdx.x;
    float v = fmaxf(in[row * 256 + c], 0.f);
    __shared__ float sh[16];
    int lane = c & 31, wid = c >> 5;
    float rs = wsum(v), rq = wsum(v * v);
    if (lane == 0) { sh[wid] = rs; sh[8 + wid] = rq; }
    __syncthreads();
    float ts = 0.f, tq = 0.f;
    #pragma unroll
    for (int i = 0; i < 8; i++) { ts += sh[i]; tq += sh[8 + i]; }
    float u = ts * (1.f / 256.f);
    float var = tq * (1.f / 256.f) - u * u;
    float o = w[c] * (v - u) * rsqrtf(var + 1e-12f) + b[c];
    out[row * 256 + c] = o;
    __half hh = __float2half_rn(o);
    outH[row * 256 + c] = hh;
    outL[row * 256 + c] = __float2half_rn(o - __half2float(hh));
}

// --------------------------- rel attention ----------------------------------
__global__ void __launch_bounds__(256) rel_attn(
    const float* __restrict__ cen,   // [B,768]
    const float* __restrict__ kvr,   // [NPOS,512]
    float* __restrict__ rctx)        // [B,256]
{
    int n = blockIdx.x >> 3, h = blockIdx.x & 7;
    int w = threadIdx.x >> 5, lane = threadIdx.x & 31;
    int off = h * 32 + lane;
    float qv = cen[n * 768 + off];
    float m = -1e30f, s = 0.f, acc = 0.f;
    for (int t = w; t <= L_; t += 8) {
        float kv, vv;
        if (t == 0) { kv = cen[n * 768 + 256 + off]; vv = cen[n * 768 + 512 + off]; }
        else {
            long r = (long)n * L_ + (t - 1);
            kv = kvr[r * 512 + off];
            vv = kvr[r * 512 + 256 + off];
        }
        float d = wsum(qv * kv) * SCALE_;
        float mn = fmaxf(m, d);
        float eo = __expf(m - mn);
        float en = __expf(d - mn);
        s = s * eo + en;
        acc = acc * eo + en * vv;
        m = mn;
    }
    __shared__ float sm[8], ss[8], sacc[8][32];
    sacc[w][lane] = acc;
    if (lane == 0) { sm[w] = m; ss[w] = s; }
    __syncthreads();
    if (w == 0) {
        float M = sm[0];
        #pragma unroll
        for (int r = 1; r < 8; r++) M = fmaxf(M, sm[r]);
        float S = 0.f, A = 0.f;
        #pragma unroll
        for (int r = 0; r < 8; r++) {
            float f = __expf(sm[r] - M);
            S += ss[r] * f;
            A += sacc[r][lane] * f;
        }
        rctx[n * 256 + off] = A / S;
    }
}

// ---------------- rel output: rctx@Wo + bo + center, relu, LN ---------------
__global__ void __launch_bounds__(256) rel_out(
    const float* __restrict__ rctx, const float* __restrict__ Wo,
    const float* __restrict__ bo, float* __restrict__ center,
    const float* __restrict__ lnw, const float* __restrict__ lnb)
{
    int n = blockIdx.x, c = threadIdx.x;
    __shared__ float sa[256];
    sa[c] = rctx[n * 256 + c];
    __syncthreads();
    float o = bo[c] + center[n * 256 + c];
    #pragma unroll 8
    for (int k = 0; k < 256; k++) o += sa[k] * Wo[k * 256 + c];
    o = fmaxf(o, 0.f);
    __shared__ float sh[16];
    int lane = c & 31, wid = c >> 5;
    float rs = wsum(o), rq = wsum(o * o);
    if (lane == 0) { sh[wid] = rs; sh[8 + wid] = rq; }
    __syncthreads();
    float ts = 0.f, tq = 0.f;
    #pragma unroll
    for (int i = 0; i < 8; i++) { ts += sh[i]; tq += sh[8 + i]; }
    float u = ts * (1.f / 256.f);
    float var = tq * (1.f / 256.f) - u * u;
    center[n * 256 + c] = lnw[c] * (o - u) * rsqrtf(var + 1e-12f) + lnb[c];
}

// ------------------------------- output tail --------------------------------
__global__ void write_tail(const float* __restrict__ center,
                           float* __restrict__ out, int ncur, int ntot)
{
    int i = ncur + blockIdx.x * 256 + threadIdx.x;
    if (i < ntot) {
        int j = i - ncur;
        out[i] = (j < B_ * H_) ? center[j] : 0.f;
    }
}

// ------------------------------- host side ----------------------------------
extern "C" void kernel_launch(void* const* d_in, const int* in_sizes, int n_in,
                              void* d_out, int out_size)
{
    const float* x    = (const float*)d_in[0];
    const float* sWq  = (const float*)d_in[1];
    const float* sbq  = (const float*)d_in[2];
    const float* sWk  = (const float*)d_in[3];
    const float* sbk  = (const float*)d_in[4];
    const float* sWv  = (const float*)d_in[5];
    const float* sbv  = (const float*)d_in[6];
    const float* sWo  = (const float*)d_in[7];
    const float* sbo  = (const float*)d_in[8];
    const float* rWq  = (const float*)d_in[9];
    const float* rbq  = (const float*)d_in[10];
    const float* rWk  = (const float*)d_in[11];
    const float* rbk  = (const float*)d_in[12];
    const float* rWv  = (const float*)d_in[13];
    const float* rbv  = (const float*)d_in[14];
    const float* rWo  = (const float*)d_in[15];
    const float* rbo  = (const float*)d_in[16];
    const float* slnw = (const float*)d_in[17];
    const float* slnb = (const float*)d_in[18];
    const float* rlnw = (const float*)d_in[19];
    const float* rlnb = (const float*)d_in[20];

    float *QKVc, *KVx, *KVr, *satpre, *cur, *center, *part;
    float *cenSat, *cenRel, *rctx, *satW, *relW, *satB, *relB;
    __half *xH, *xL, *ctxH, *ctxL, *curH, *curL, *sWt, *rWt, *sWoT;
    cudaGetSymbolAddress((void**)&QKVc,   g_QKVc);
    cudaGetSymbolAddress((void**)&KVx,    g_KVx);
    cudaGetSymbolAddress((void**)&KVr,    g_KVr);
    cudaGetSymbolAddress((void**)&satpre, g_satpre);
    cudaGetSymbolAddress((void**)&cur,    g_cur);
    cudaGetSymbolAddress((void**)&center, g_center);
    cudaGetSymbolAddress((void**)&part,   g_part);
    cudaGetSymbolAddress((void**)&cenSat, g_cenSat);
    cudaGetSymbolAddress((void**)&cenRel, g_cenRel);
    cudaGetSymbolAddress((void**)&rctx,   g_rctx);
    cudaGetSymbolAddress((void**)&satW,   g_satW);
    cudaGetSymbolAddress((void**)&relW,   g_relW);
    cudaGetSymbolAddress((void**)&satB,   g_satBias);
    cudaGetSymbolAddress((void**)&relB,   g_relBias);
    cudaGetSymbolAddress((void**)&xH,     g_xH);
    cudaGetSymbolAddress((void**)&xL,     g_xL);
    cudaGetSymbolAddress((void**)&ctxH,   g_ctxH);
    cudaGetSymbolAddress((void**)&ctxL,   g_ctxL);
    cudaGetSymbolAddress((void**)&curH,   g_curH);
    cudaGetSymbolAddress((void**)&curL,   g_curL);
    cudaGetSymbolAddress((void**)&sWt,    g_sWt);
    cudaGetSymbolAddress((void**)&rWt,    g_rWt);
    cudaGetSymbolAddress((void**)&sWoT,   g_sWoT);

    cudaFuncSetAttribute(gemm_mma, cudaFuncAttributeMaxDynamicSharedMemorySize, GSMEM_DYN);

    // 5 launches before the first GEMM (ncu -s 5 -c 1 captures gemm_mma)
    pack_w<<<768, 256>>>(sWq, sWk, sWv, sbq, sbk, sbv, satW, satB);
    pack_w<<<768, 256>>>(rWq, rWk, rWv, rbq, rbk, rbv, relW, relB);
    pack_wt_all<<<1792, 256>>>(sWq, sWk, sWv, rWq, rWk, rWv, sWo, sWt, rWt, sWoT);
    split_a<<<NPOS * 256 / 1024, 256>>>(x, xH, xL);
    mean_stage1<<<dim3(32, B_), 256>>>(x, part);

    // K/V of x (once) — 6th launch
    gemm_mma<<<dim3(4, NPOS / 128), 256, GSMEM_DYN>>>(
        xH, xL, sWt + 256 * 256, satB + 256, nullptr, 0, KVx, 512);

    mean_stage2<<<B_, 256>>>(part, center);

    for (int it = 0; it < 2; it++) {
        const __half* aH = (it == 0) ? xH : curH;
        const __half* aL = (it == 0) ? xL : curL;
        const float* resf = (it == 0) ? x : cur;
        float* lnDst = (it == 0) ? cur : (float*)d_out;

        cen_proj<<<24, 256>>>(center, satW, satB, cenSat);
        gemm_mma<<<dim3(6, NPOS / 128), 256, GSMEM_DYN>>>(
            aH, aL, sWt, satB, nullptr, 0, QKVc, 768);
        sat_attn<<<NPOS / 8, 256>>>(QKVc, KVx, cenSat, ctxH, ctxL);
        gemm_mma<<<dim3(2, NPOS / 128), 256, GSMEM_DYN>>>(
            ctxH, ctxL, sWoT, sbo, resf, 256, satpre, 256);
        relu_ln<<<NPOS, 256>>>(satpre, slnw, slnb, lnDst, curH, curL);

        cen_proj<<<24, 256>>>(center, relW, relB, cenRel);
        gemm_mma<<<dim3(4, NPOS / 128), 256, GSMEM_DYN>>>(
            curH, curL, rWt + 256 * 256, relB + 256, nullptr, 0, KVr, 512);
        rel_attn<<<B_ * 8, 256>>>(cenRel, KVr, rctx);
        rel_out<<<B_, 256>>>(rctx, rWo, rbo, center, rlnw, rlnb);
    }

    int ncur = NPOS * H_;
    int tail = out_size - ncur;
    if (tail > 0)
        write_tail<<<(tail + 255) / 256, 256>>>(center, (float*)d_out, ncur, out_size);
}

// round 14
// speedup vs baseline: 2.0445x; 1.0649x over previous
#include <cuda_runtime.h>
#include <cuda_bf16.h>
#include <cuda_fp16.h>
#include <cstdint>

// ---------------------------------------------------------------------------
// StarTransformerLayer  B=8 L=4096 H=256 NH=8 HD=32, 2 iterations.
// Round 11: fp16 2-product HMMA GEMM, K-chunk 64 (half the barriers),
// SW128 swizzle, cp.async 2-stage; Wo-GEMM fused with bias+res+relu+LN+split
// (tile 64x256).  gemm_mma is the 4th launch so ncu captures it.
// ---------------------------------------------------------------------------

#define B_   8
#define L_   4096
#define H_   256
#define NPOS (B_*L_)              // 32768
#define SCALE_ 0.17677669529663689f   // 1/sqrt(32)

// ------------------------- scratch (device globals) ------------------------
__device__ float g_QKVc [NPOS*768];
__device__ float g_KVx  [NPOS*512];
__device__ float g_KVr  [NPOS*512];
__device__ float g_cur  [NPOS*256];
__device__ float g_center[B_*H_];
__device__ float g_part [B_*32*H_];
__device__ float g_cenSat[B_*768];
__device__ float g_cenRel[B_*768];
__device__ float g_rctx [B_*H_];
__device__ float g_satW [256*768];
__device__ float g_relW [256*768];
__device__ float g_satBias[768];
__device__ float g_relBias[768];
// pre-split fp16 hi/lo activations (GEMM A operands)
__device__ __half g_xH  [NPOS*256];
__device__ __half g_xL  [NPOS*256];
__device__ __half g_ctxH[NPOS*256];
__device__ __half g_ctxL[NPOS*256];
__device__ __half g_curH[NPOS*256];
__device__ __half g_curL[NPOS*256];
// transposed weights: [N,256] K-major fp16
__device__ __half g_sWt [768*256];
__device__ __half g_rWt [768*256];
__device__ __half g_sWoT[256*256];

// ------------------------------ helpers -------------------------------------
__device__ __forceinline__ uint32_t su32(const void* p) {
    return (uint32_t)__cvta_generic_to_shared(p);
}
__device__ __forceinline__ uint32_t swz128(uint32_t o) {   // 128B-row swizzle
    return o ^ ((o >> 3) & 0x70);
}
__device__ __forceinline__ void cpa16(uint32_t saddr, const void* g) {
    asm volatile("cp.async.cg.shared.global [%0], [%1], 16;"
                 :: "r"(saddr), "l"(g));
}
__device__ __forceinline__ void ldm4(uint32_t* r, uint32_t addr) {
    asm volatile("ldmatrix.sync.aligned.m8n8.x4.shared.b16 {%0,%1,%2,%3}, [%4];"
                 : "=r"(r[0]), "=r"(r[1]), "=r"(r[2]), "=r"(r[3]) : "r"(addr));
}
__device__ __forceinline__ void mma16816h(float* d, const uint32_t* a,
                                          uint32_t b0, uint32_t b1) {
    asm volatile(
        "mma.sync.aligned.m16n8k16.row.col.f32.f16.f16.f32 "
        "{%0,%1,%2,%3}, {%4,%5,%6,%7}, {%8,%9}, {%0,%1,%2,%3};"
        : "+f"(d[0]), "+f"(d[1]), "+f"(d[2]), "+f"(d[3])
        : "r"(a[0]), "r"(a[1]), "r"(a[2]), "r"(a[3]), "r"(b0), "r"(b1));
}
__device__ __forceinline__ float wsum(float v) {
    v += __shfl_xor_sync(0xffffffffu, v, 16);
    v += __shfl_xor_sync(0xffffffffu, v, 8);
    v += __shfl_xor_sync(0xffffffffu, v, 4);
    v += __shfl_xor_sync(0xffffffffu, v, 2);
    v += __shfl_xor_sync(0xffffffffu, v, 1);
    return v;
}

// =========================== HMMA GEMM (128x128) ============================
// C[M,N] = (Ah+Al)[M,256] @ B^T + bias.   K chunks of 64, 2-stage cp.async.
#define STGB_  49152           // Ah 16K | Al 16K | B 16K per stage
#define GSMEM_DYN (2*STGB_ + 1024)

__global__ void __launch_bounds__(256, 2) gemm_mma(
    const __half* __restrict__ Ah,   // [M,256]
    const __half* __restrict__ Al,
    const __half* __restrict__ Bt,   // [N,256] K-major
    const float* __restrict__ bias,
    float* __restrict__ C, int ldc)
{
    extern __shared__ char smem_raw[];
    char* smem = (char*)(((uintptr_t)smem_raw + 1023) & ~(uintptr_t)1023);
    const uint32_t sbase = su32(smem);

    const int tid  = threadIdx.x;
    const int wid  = tid >> 5;
    const int lane = tid & 31;
    const int wm = wid >> 2;        // 0..1
    const int wn = wid & 3;         // 0..3
    const int m0 = blockIdx.y * 128;
    const int n0 = blockIdx.x * 128;

    const int frow = tid >> 3;      // 0..31 (row block within fill)
    const int fq   = tid & 7;       // 16B column within 128B row

    float acc[4][4][4];
    #pragma unroll
    for (int i = 0; i < 4; i++)
        #pragma unroll
        for (int j = 0; j < 4; j++)
            #pragma unroll
            for (int t = 0; t < 4; t++) acc[i][j][t] = 0.f;

    const int aR = lane & 15;
    const int aC16 = lane >> 4;
    const int bN = (lane & 7) + ((lane >> 1) & 8);
    const int bK8 = (lane >> 3) & 1;

    auto load_stage = [&](int c, int s) {
        uint32_t st = sbase + (uint32_t)s * STGB_;
        #pragma unroll
        for (int j = 0; j < 4; j++) {       // A hi: 128 rows
            int row = j * 32 + frow;
            uint32_t so = swz128(row * 128 + fq * 16);
            cpa16(st + so, Ah + (long)(m0 + row) * 256 + c * 64 + fq * 8);
        }
        #pragma unroll
        for (int j = 0; j < 4; j++) {       // A lo
            int row = j * 32 + frow;
            uint32_t so = swz128(row * 128 + fq * 16);
            cpa16(st + 16384u + so, Al + (long)(m0 + row) * 256 + c * 64 + fq * 8);
        }
        #pragma unroll
        for (int j = 0; j < 4; j++) {       // B
            int row = j * 32 + frow;
            uint32_t so = swz128(row * 128 + fq * 16);
            cpa16(st + 32768u + so, Bt + (long)(n0 + row) * 256 + c * 64 + fq * 8);
        }
    };

    load_stage(0, 0);
    asm volatile("cp.async.commit_group;" ::: "memory");

    for (int c = 0; c < 4; c++) {
        if (c + 1 < 4) {
            load_stage(c + 1, (c + 1) & 1);
            asm volatile("cp.async.commit_group;" ::: "memory");
            asm volatile("cp.async.wait_group 1;" ::: "memory");
        } else {
            asm volatile("cp.async.wait_group 0;" ::: "memory");
        }
        __syncthreads();

        const uint32_t st = sbase + (uint32_t)(c & 1) * STGB_;
        const uint32_t uAh = st, uAl = st + 16384u, uBt = st + 32768u;

        #pragma unroll
        for (int ks = 0; ks < 4; ks++) {
            uint32_t bf[2][4];
            #pragma unroll
            for (int ng = 0; ng < 2; ng++) {
                uint32_t boff = swz128((uint32_t)(wn * 32 + ng * 16 + bN) * 128
                                       + ks * 32 + bK8 * 16);
                ldm4(bf[ng], uBt + boff);
            }
            #pragma unroll
            for (int mt = 0; mt < 4; mt++) {
                uint32_t ah[4], al[4];
                uint32_t aoff = swz128((uint32_t)(wm * 64 + mt * 16 + aR) * 128
                                       + ks * 32 + aC16 * 16);
                ldm4(ah, uAh + aoff);
                ldm4(al, uAl + aoff);
                #pragma unroll
                for (int nt = 0; nt < 4; nt++) {
                    const int ng = nt >> 1, sb = (nt & 1) * 2;
                    mma16816h(acc[mt][nt], ah, bf[ng][sb], bf[ng][sb + 1]);
                    mma16816h(acc[mt][nt], al, bf[ng][sb], bf[ng][sb + 1]);
                }
            }
        }
        __syncthreads();
    }

    // ---- epilogue ----
    const int er = lane >> 2;
    const int ec = (lane & 3) * 2;
    #pragma unroll
    for (int mt = 0; mt < 4; mt++) {
        #pragma unroll
        for (int nt = 0; nt < 4; nt++) {
            const long m = m0 + wm * 64 + mt * 16 + er;
            const int  n = n0 + wn * 32 + nt * 8 + ec;
            float bx = bias[n], by = bias[n + 1];
            float2 o0, o1;
            o0.x = acc[mt][nt][0] + bx; o0.y = acc[mt][nt][1] + by;
            o1.x = acc[mt][nt][2] + bx; o1.y = acc[mt][nt][3] + by;
            *(float2*)(C + m * ldc + n) = o0;
            *(float2*)(C + (m + 8) * ldc + n) = o1;
        }
    }
}

// ============ fused Wo GEMM + bias + residual + relu + LN + split ===========
// Tile 64x256 (CTA owns full rows).  Stage: Ah 8K | Al 8K | B 32K = 48K.
#define LNSTR_ 264

__global__ void __launch_bounds__(256, 2) gemm_wo_ln(
    const __half* __restrict__ Ah,   // ctx hi  [M,256]
    const __half* __restrict__ Al,   // ctx lo
    const __half* __restrict__ Bt,   // WoT fp16 [256,256] K-major
    const float* __restrict__ bo,
    const float* __restrict__ res,   // residual fp32 [M,256]
    const float* __restrict__ lnw, const float* __restrict__ lnb,
    float* __restrict__ outF,
    __half* __restrict__ outH, __half* __restrict__ outL)
{
    extern __shared__ char smem_raw[];
    char* smem = (char*)(((uintptr_t)smem_raw + 1023) & ~(uintptr_t)1023);
    const uint32_t sbase = su32(smem);

    const int tid  = threadIdx.x;
    const int wid  = tid >> 5;
    const int lane = tid & 31;
    const int wm = wid >> 2;        // 0..1 (32-row block)
    const int wn = wid & 3;         // 0..3 (64-col block)
    const int m0 = blockIdx.x * 64;

    const int frow = tid >> 3;
    const int fq   = tid & 7;

    float acc[2][8][4];
    #pragma unroll
    for (int i = 0; i < 2; i++)
        #pragma unroll
        for (int j = 0; j < 8; j++)
            #pragma unroll
            for (int t = 0; t < 4; t++) acc[i][j][t] = 0.f;

    const int aR = lane & 15;
    const int aC16 = lane >> 4;
    const int bN = (lane & 7) + ((lane >> 1) & 8);
    const int bK8 = (lane >> 3) & 1;

    auto load_stage = [&](int c, int s) {
        uint32_t st = sbase + (uint32_t)s * STGB_;
        #pragma unroll
        for (int j = 0; j < 2; j++) {       // A hi: 64 rows
            int row = j * 32 + frow;
            uint32_t so = swz128(row * 128 + fq * 16);
            cpa16(st + so, Ah + (long)(m0 + row) * 256 + c * 64 + fq * 8);
        }
        #pragma unroll
        for (int j = 0; j < 2; j++) {       // A lo
            int row = j * 32 + frow;
            uint32_t so = swz128(row * 128 + fq * 16);
            cpa16(st + 8192u + so, Al + (long)(m0 + row) * 256 + c * 64 + fq * 8);
        }
        #pragma unroll
        for (int j = 0; j < 8; j++) {       // B: 256 rows
            int row = j * 32 + frow;
            uint32_t so = swz128(row * 128 + fq * 16);
            cpa16(st + 16384u + so, Bt + (long)row * 256 + c * 64 + fq * 8);
        }
    };

    load_stage(0, 0);
    asm volatile("cp.async.commit_group;" ::: "memory");

    for (int c = 0; c < 4; c++) {
        if (c + 1 < 4) {
            load_stage(c + 1, (c + 1) & 1);
            asm volatile("cp.async.commit_group;" ::: "memory");
            asm volatile("cp.async.wait_group 1;" ::: "memory");
        } else {
            asm volatile("cp.async.wait_group 0;" ::: "memory");
        }
        __syncthreads();

        const uint32_t st = sbase + (uint32_t)(c & 1) * STGB_;
        const uint32_t uAh = st, uAl = st + 8192u, uBt = st + 16384u;

        #pragma unroll
        for (int ks = 0; ks < 4; ks++) {
            uint32_t bf[4][4];
            #pragma unroll
            for (int ng = 0; ng < 4; ng++) {
                uint32_t boff = swz128((uint32_t)(wn * 64 + ng * 16 + bN) * 128
                                       + ks * 32 + bK8 * 16);
                ldm4(bf[ng], uBt + boff);
            }
            #pragma unroll
            for (int mt = 0; mt < 2; mt++) {
                uint32_t ah[4], al[4];
                uint32_t aoff = swz128((uint32_t)(wm * 32 + mt * 16 + aR) * 128
                                       + ks * 32 + aC16 * 16);
                ldm4(ah, uAh + aoff);
                ldm4(al, uAl + aoff);
                #pragma unroll
                for (int nt = 0; nt < 8; nt++) {
                    const int ng = nt >> 1, sb = (nt & 1) * 2;
                    mma16816h(acc[mt][nt], ah, bf[ng][sb], bf[ng][sb + 1]);
                    mma16816h(acc[mt][nt], al, bf[ng][sb], bf[ng][sb + 1]);
                }
            }
        }
        __syncthreads();
    }

    // ---- bias + residual + relu -> smem [64][LNSTR_] ----
    float* S = (float*)smem;
    const int er = lane >> 2;
    const int ec = (lane & 3) * 2;
    #pragma unroll
    for (int mt = 0; mt < 2; mt++) {
        #pragma unroll
        for (int nt = 0; nt < 8; nt++) {
            const int r0 = wm * 32 + mt * 16 + er;
            const int n = wn * 64 + nt * 8 + ec;
            const long m = m0 + r0;
            float bx = bo[n], by = bo[n + 1];
            float2 rr0 = *(const float2*)(res + m * 256 + n);
            float2 rr1 = *(const float2*)(res + (m + 8) * 256 + n);
            float2 o0, o1;
            o0.x = fmaxf(acc[mt][nt][0] + bx + rr0.x, 0.f);
            o0.y = fmaxf(acc[mt][nt][1] + by + rr0.y, 0.f);
            o1.x = fmaxf(acc[mt][nt][2] + bx + rr1.x, 0.f);
            o1.y = fmaxf(acc[mt][nt][3] + by + rr1.y, 0.f);
            *(float2*)&S[r0 * LNSTR_ + n] = o0;
            *(float2*)&S[(r0 + 8) * LNSTR_ + n] = o1;
        }
    }
    __syncthreads();

    // ---- per-row LayerNorm: warp w handles rows w, w+8, ..., w+56 ----
    #pragma unroll
    for (int rr = 0; rr < 8; rr++) {
        const int r = wid + rr * 8;
        float v[8], s1 = 0.f, s2 = 0.f;
        #pragma unroll
        for (int i = 0; i < 8; i++) {
            v[i] = S[r * LNSTR_ + lane + i * 32];
            s1 += v[i];
            s2 += v[i] * v[i];
        }
        s1 = wsum(s1); s2 = wsum(s2);
        float u = s1 * (1.f / 256.f);
        float var = s2 * (1.f / 256.f) - u * u;
        float inv = rsqrtf(var + 1e-12f);
        const long m = m0 + r;
        #pragma unroll
        for (int i = 0; i < 8; i++) {
            const int cc = lane + i * 32;
            float o = lnw[cc] * (v[i] - u) * inv + lnb[cc];
            outF[m * 256 + cc] = o;
            __half hh = __float2half_rn(o);
            outH[m * 256 + cc] = hh;
            outL[m * 256 + cc] = __float2half_rn(o - __half2float(hh));
        }
    }
}

// ------------------------- fp32 -> fp16 hi/lo split -------------------------
__global__ void __launch_bounds__(256) split_a(
    const float* __restrict__ a,
    __half* __restrict__ h, __half* __restrict__ l)
{
    int i = blockIdx.x * 256 + threadIdx.x;     // float4 index
    float4 v = ((const float4*)a)[i];
    __half hx = __float2half_rn(v.x);
    __half hy = __float2half_rn(v.y);
    __half hz = __float2half_rn(v.z);
    __half hw = __float2half_rn(v.w);
    __half2* hp = (__half2*)(h + i * 4);
    __half2* lp = (__half2*)(l + i * 4);
    __half2 h0; h0.x = hx; h0.y = hy;
    __half2 h1; h1.x = hz; h1.y = hw;
    __half2 l0, l1;
    l0.x = __float2half_rn(v.x - __half2float(hx));
    l0.y = __float2half_rn(v.y - __half2float(hy));
    l1.x = __float2half_rn(v.z - __half2float(hz));
    l1.y = __float2half_rn(v.w - __half2float(hw));
    hp[0] = h0; hp[1] = h1;
    lp[0] = l0; lp[1] = l1;
}

// ------------------------- weight/bias packing ------------------------------
__global__ void __launch_bounds__(256) pack_w(
    const float* __restrict__ Wq, const float* __restrict__ Wk, const float* __restrict__ Wv,
    const float* __restrict__ bq, const float* __restrict__ bk, const float* __restrict__ bv,
    float* __restrict__ Wp, float* __restrict__ bp)
{
    int idx = blockIdx.x * 256 + threadIdx.x;
    int k = idx / 768, c = idx % 768;
    int sel = c >> 8, cc = c & 255;
    const float* W = (sel == 0) ? Wq : (sel == 1) ? Wk : Wv;
    Wp[idx] = W[k * 256 + cc];
    if (idx < 768) {
        const float* b = (sel == 0) ? bq : (sel == 1) ? bk : bv;
        bp[idx] = b[cc];
    }
}

__global__ void __launch_bounds__(256) pack_wt_all(
    const float* __restrict__ sWq, const float* __restrict__ sWk, const float* __restrict__ sWv,
    const float* __restrict__ rWq, const float* __restrict__ rWk, const float* __restrict__ rWv,
    const float* __restrict__ sWo,
    __half* __restrict__ sWt, __half* __restrict__ rWt, __half* __restrict__ sWoT)
{
    int blk = blockIdx.x;                 // 0..1791
    if (blk < 768) {
        int idx = blk * 256 + threadIdx.x;
        int n = idx >> 8, k = idx & 255;
        int sel = n >> 8, nc = n & 255;
        const float* W = (sel == 0) ? sWq : (sel == 1) ? sWk : sWv;
        sWt[idx] = __float2half_rn(W[k * 256 + nc]);
    } else if (blk < 1536) {
        int idx = (blk - 768) * 256 + threadIdx.x;
        int n = idx >> 8, k = idx & 255;
        int sel = n >> 8, nc = n & 255;
        const float* W = (sel == 0) ? rWq : (sel == 1) ? rWk : rWv;
        rWt[idx] = __float2half_rn(W[k * 256 + nc]);
    } else {
        int idx = (blk - 1536) * 256 + threadIdx.x;
        int n = idx >> 8, k = idx & 255;
        sWoT[idx] = __float2half_rn(sWo[k * 256 + n]);
    }
}

// ------------------------------ mean over L ---------------------------------
__global__ void __launch_bounds__(256) mean_stage1(const float* __restrict__ x,
                                                   float* __restrict__ part)
{
    int s = blockIdx.x, n = blockIdx.y, c = threadIdx.x;
    const float* base = x + ((long)n * L_ + (long)s * 128) * H_ + c;
    float sum = 0.f;
    #pragma unroll 8
    for (int l = 0; l < 128; l++) sum += base[(long)l * H_];
    part[(n * 32 + s) * H_ + c] = sum;
}

__global__ void __launch_bounds__(256) mean_stage2(const float* __restrict__ part,
                                                   float* __restrict__ center)
{
    int n = blockIdx.x, c = threadIdx.x;
    float sum = 0.f;
    #pragma unroll
    for (int s = 0; s < 32; s++) sum += part[(n * 32 + s) * H_ + c];
    center[n * H_ + c] = sum * (1.f / (float)L_);
}

// ---------------------- tiny projection: center @ Wpack ---------------------
__global__ void __launch_bounds__(256) cen_proj(
    const float* __restrict__ center, const float* __restrict__ Wp,
    const float* __restrict__ bp, float* __restrict__ out)
{
    __shared__ float sh[256];
    int idx = blockIdx.x * 256 + threadIdx.x;
    int r = idx / 768, c = idx % 768;
    sh[threadIdx.x] = center[r * 256 + threadIdx.x];
    __syncthreads();
    float s = bp[c];
    #pragma unroll 8
    for (int k = 0; k < 256; k++) s += sh[k] * Wp[k * 768 + c];
    out[idx] = s;
}

// --------------------------- sat attention ----------------------------------
__global__ void __launch_bounds__(256) sat_attn(
    const float* __restrict__ qkv,    // [NPOS,768]
    const float* __restrict__ kvx,    // [NPOS,512]
    const float* __restrict__ cen,    // [B,768]
    __half* __restrict__ ctxH,
    __half* __restrict__ ctxL)
{
    int warp = (blockIdx.x * blockDim.x + threadIdx.x) >> 5;
    int lane = threadIdx.x & 31;
    if (warp >= NPOS) return;
    int n = warp >> 12;
    int l = warp & (L_ - 1);
    long i  = warp;
    long rb = (long)n * L_ + ((l + 1 == L_) ? 0 : l + 1);
    long ra = (long)n * L_ + ((l == 0) ? (L_ - 1) : 0);

    #pragma unroll
    for (int h = 0; h < 8; h++) {
        int off = h * 32 + lane;
        float qv = qkv[i * 768 + off];
        float k0 = qkv[rb * 768 + 256 + off];
        float k1 = qkv[i  * 768 + 256 + off];
        float k2 = qkv[ra * 768 + 256 + off];
        float k3 = kvx[i * 512 + off];
        float k4 = cen[n * 768 + 256 + off];
        float s0 = wsum(qv * k0) * SCALE_;
        float s1 = wsum(qv * k1) * SCALE_;
        float s2 = wsum(qv * k2) * SCALE_;
        float s3 = wsum(qv * k3) * SCALE_;
        float s4 = wsum(qv * k4) * SCALE_;
        float m = fmaxf(fmaxf(fmaxf(s0, s1), fmaxf(s2, s3)), s4);
        float p0 = __expf(s0 - m), p1 = __expf(s1 - m), p2 = __expf(s2 - m);
        float p3 = __expf(s3 - m), p4 = __expf(s4 - m);
        float den = p0 + p1 + p2 + p3 + p4;
        float v0 = qkv[rb * 768 + 512 + off];
        float v1 = qkv[i  * 768 + 512 + off];
        float v2 = qkv[ra * 768 + 512 + off];
        float v3 = kvx[i * 512 + 256 + off];
        float v4 = cen[n * 768 + 512 + off];
        float o = (p0 * v0 + p1 * v1 + p2 * v2 + p3 * v3 + p4 * v4) / den;
        __half hh = __float2half_rn(o);
        ctxH[i * 256 + off] = hh;
        ctxL[i * 256 + off] = __float2half_rn(o - __half2float(hh));
    }
}

// --------------------------- rel attention ----------------------------------
__global__ void __launch_bounds__(256) rel_attn(
    const float* __restrict__ cen,   // [B,768]
    const float* __restrict__ kvr,   // [NPOS,512]
    float* __restrict__ rctx)        // [B,256]
{
    int n = blockIdx.x >> 3, h = blockIdx.x & 7;
    int w = threadIdx.x >> 5, lane = threadIdx.x & 31;
    int off = h * 32 + lane;
    float qv = cen[n * 768 + off];
    float m = -1e30f, s = 0.f, acc = 0.f;
    for (int t = w; t <= L_; t += 8) {
        float kv, vv;
        if (t == 0) { kv = cen[n * 768 + 256 + off]; vv = cen[n * 768 + 512 + off]; }
        else {
            long r = (long)n * L_ + (t - 1);
            kv = kvr[r * 512 + off];
            vv = kvr[r * 512 + 256 + off];
        }
        float d = wsum(qv * kv) * SCALE_;
        float mn = fmaxf(m, d);
        float eo = __expf(m - mn);
        float en = __expf(d - mn);
        s = s * eo + en;
        acc = acc * eo + en * vv;
        m = mn;
    }
    __shared__ float sm[8], ss[8], sacc[8][32];
    sacc[w][lane] = acc;
    if (lane == 0) { sm[w] = m; ss[w] = s; }
    __syncthreads();
    if (w == 0) {
        float M = sm[0];
        #pragma unroll
        for (int r = 1; r < 8; r++) M = fmaxf(M, sm[r]);
        float S = 0.f, A = 0.f;
        #pragma unroll
        for (int r = 0; r < 8; r++) {
            float f = __expf(sm[r] - M);
            S += ss[r] * f;
            A += sacc[r][lane] * f;
        }
        rctx[n * 256 + off] = A / S;
    }
}

// ---------------- rel output: rctx@Wo + bo + center, relu, LN ---------------
__global__ void __launch_bounds__(256) rel_out(
    const float* __restrict__ rctx, const float* __restrict__ Wo,
    const float* __restrict__ bo, float* __restrict__ center,
    const float* __restrict__ lnw, const float* __restrict__ lnb)
{
    int n = blockIdx.x, c = threadIdx.x;
    __shared__ float sa[256];
    sa[c] = rctx[n * 256 + c];
    __syncthreads();
    float o = bo[c] + center[n * 256 + c];
    #pragma unroll 8
    for (int k = 0; k < 256; k++) o += sa[k] * Wo[k * 256 + c];
    o = fmaxf(o, 0.f);
    __shared__ float sh[16];
    int lane = c & 31, wid = c >> 5;
    float rs = wsum(o), rq = wsum(o * o);
    if (lane == 0) { sh[wid] = rs; sh[8 + wid] = rq; }
    __syncthreads();
    float ts = 0.f, tq = 0.f;
    #pragma unroll
    for (int i = 0; i < 8; i++) { ts += sh[i]; tq += sh[8 + i]; }
    float u = ts * (1.f / 256.f);
    float var = tq * (1.f / 256.f) - u * u;
    center[n * 256 + c] = lnw[c] * (o - u) * rsqrtf(var + 1e-12f) + lnb[c];
}

// ------------------------------- output tail --------------------------------
__global__ void write_tail(const float* __restrict__ center,
                           float* __restrict__ out, int ncur, int ntot)
{
    int i = ncur + blockIdx.x * 256 + threadIdx.x;
    if (i < ntot) {
        int j = i - ncur;
        out[i] = (j < B_ * H_) ? center[j] : 0.f;
    }
}

// ------------------------------- host side ----------------------------------
extern "C" void kernel_launch(void* const* d_in, const int* in_sizes, int n_in,
                              void* d_out, int out_size)
{
    const float* x    = (const float*)d_in[0];
    const float* sWq  = (const float*)d_in[1];
    const float* sbq  = (const float*)d_in[2];
    const float* sWk  = (const float*)d_in[3];
    const float* sbk  = (const float*)d_in[4];
    const float* sWv  = (const float*)d_in[5];
    const float* sbv  = (const float*)d_in[6];
    const float* sWo  = (const float*)d_in[7];
    const float* sbo  = (const float*)d_in[8];
    const float* rWq  = (const float*)d_in[9];
    const float* rbq  = (const float*)d_in[10];
    const float* rWk  = (const float*)d_in[11];
    const float* rbk  = (const float*)d_in[12];
    const float* rWv  = (const float*)d_in[13];
    const float* rbv  = (const float*)d_in[14];
    const float* rWo  = (const float*)d_in[15];
    const float* rbo  = (const float*)d_in[16];
    const float* slnw = (const float*)d_in[17];
    const float* slnb = (const float*)d_in[18];
    const float* rlnw = (const float*)d_in[19];
    const float* rlnb = (const float*)d_in[20];

    float *QKVc, *KVx, *KVr, *cur, *center, *part;
    float *cenSat, *cenRel, *rctx, *satW, *relW, *satB, *relB;
    __half *xH, *xL, *ctxH, *ctxL, *curH, *curL, *sWt, *rWt, *sWoT;
    cudaGetSymbolAddress((void**)&QKVc,   g_QKVc);
    cudaGetSymbolAddress((void**)&KVx,    g_KVx);
    cudaGetSymbolAddress((void**)&KVr,    g_KVr);
    cudaGetSymbolAddress((void**)&cur,    g_cur);
    cudaGetSymbolAddress((void**)&center, g_center);
    cudaGetSymbolAddress((void**)&part,   g_part);
    cudaGetSymbolAddress((void**)&cenSat, g_cenSat);
    cudaGetSymbolAddress((void**)&cenRel, g_cenRel);
    cudaGetSymbolAddress((void**)&rctx,   g_rctx);
    cudaGetSymbolAddress((void**)&satW,   g_satW);
    cudaGetSymbolAddress((void**)&relW,   g_relW);
    cudaGetSymbolAddress((void**)&satB,   g_satBias);
    cudaGetSymbolAddress((void**)&relB,   g_relBias);
    cudaGetSymbolAddress((void**)&xH,     g_xH);
    cudaGetSymbolAddress((void**)&xL,     g_xL);
    cudaGetSymbolAddress((void**)&ctxH,   g_ctxH);
    cudaGetSymbolAddress((void**)&ctxL,   g_ctxL);
    cudaGetSymbolAddress((void**)&curH,   g_curH);
    cudaGetSymbolAddress((void**)&curL,   g_curL);
    cudaGetSymbolAddress((void**)&sWt,    g_sWt);
    cudaGetSymbolAddress((void**)&rWt,    g_rWt);
    cudaGetSymbolAddress((void**)&sWoT,   g_sWoT);

    cudaFuncSetAttribute(gemm_mma, cudaFuncAttributeMaxDynamicSharedMemorySize, GSMEM_DYN);
    cudaFuncSetAttribute(gemm_wo_ln, cudaFuncAttributeMaxDynamicSharedMemorySize, GSMEM_DYN);

    // launch order: gemm_mma is the 4th kernel launch (ncu captures #4)
    pack_wt_all<<<1792, 256>>>(sWq, sWk, sWv, rWq, rWk, rWv, sWo, sWt, rWt, sWoT);
    split_a<<<NPOS * 256 / 1024, 256>>>(x, xH, xL);
    pack_w<<<768, 256>>>(sWq, sWk, sWv, sbq, sbk, sbv, satW, satB);

    // K/V of x (once) — 4th launch
    gemm_mma<<<dim3(4, NPOS / 128), 256, GSMEM_DYN>>>(
        xH, xL, sWt + 256 * 256, satB + 256, KVx, 512);

    pack_w<<<768, 256>>>(rWq, rWk, rWv, rbq, rbk, rbv, relW, relB);
    mean_stage1<<<dim3(32, B_), 256>>>(x, part);
    mean_stage2<<<B_, 256>>>(part, center);

    for (int it = 0; it < 2; it++) {
        const __half* aH = (it == 0) ? xH : curH;
        const __half* aL = (it == 0) ? xL : curL;
        const float* resf = (it == 0) ? x : cur;
        float* lnDst = (it == 0) ? cur : (float*)d_out;

        cen_proj<<<24, 256>>>(center, satW, satB, cenSat);
        gemm_mma<<<dim3(6, NPOS / 128), 256, GSMEM_DYN>>>(
            aH, aL, sWt, satB, QKVc, 768);
        sat_attn<<<NPOS / 8, 256>>>(QKVc, KVx, cenSat, ctxH, ctxL);
        gemm_wo_ln<<<NPOS / 64, 256, GSMEM_DYN>>>(
            ctxH, ctxL, sWoT, sbo, resf, slnw, slnb, lnDst, curH, curL);

        cen_proj<<<24, 256>>>(center, relW, relB, cenRel);
        gemm_mma<<<dim3(4, NPOS / 128), 256, GSMEM_DYN>>>(
            curH, curL, rWt + 256 * 256, relB + 256, KVr, 512);
        rel_attn<<<B_ * 8, 256>>>(cenRel, KVr, rctx);
        rel_out<<<B_, 256>>>(rctx, rWo, rbo, center, rlnw, rlnb);
    }

    int ncur = NPOS * H_;
    int tail = out_size - ncur;
    if (tail > 0)
        write_tail<<<(tail + 255) / 256, 256>>>(center, (float*)d_out, ncur, out_size);
}

// round 17
// speedup vs baseline: 3.3116x; 1.6198x over previous
#include <cuda_runtime.h>
#include <cuda_bf16.h>
#include <cuda_fp16.h>
#include <cstdint>

// ---------------------------------------------------------------------------
// StarTransformerLayer  B=8 L=4096 H=256 NH=8 HD=32, 2 iterations.
// Round 15: fp16 2-product HMMA GEMM (warp tile 32x64: 8 LDSM / 32 MMA per
// k16), QKV(x) computed once and reused as KVx (kills one GEMM), rel_attn
// split 8 ways, all weight packs in one launch.
// ---------------------------------------------------------------------------

#define B_   8
#define L_   4096
#define H_   256
#define NPOS (B_*L_)              // 32768
#define SCALE_ 0.17677669529663689f   // 1/sqrt(32)

// ------------------------- scratch (device globals) ------------------------
__device__ float g_QKVx [NPOS*768];   // QKV of x   (sat weights, persists)
__device__ float g_QKVc [NPOS*768];   // QKV of cur (iter 1)
__device__ float g_KVr  [NPOS*512];
__device__ float g_cur  [NPOS*256];
__device__ float g_center[B_*H_];
__device__ float g_part [B_*32*H_];
__device__ float g_cenSat[B_*768];
__device__ float g_cenRel[B_*768];
__device__ float g_rctx [B_*H_];
__device__ float g_rpm  [64*8];
__device__ float g_rps  [64*8];
__device__ float g_rpacc[64*8*32];
__device__ float g_satW [256*768];
__device__ float g_relW [256*768];
__device__ float g_satBias[768];
__device__ float g_relBias[768];
// pre-split fp16 hi/lo activations (GEMM A operands)
__device__ __half g_xH  [NPOS*256];
__device__ __half g_xL  [NPOS*256];
__device__ __half g_ctxH[NPOS*256];
__device__ __half g_ctxL[NPOS*256];
__device__ __half g_curH[NPOS*256];
__device__ __half g_curL[NPOS*256];
// transposed weights: [N,256] K-major fp16
__device__ __half g_sWt [768*256];
__device__ __half g_rWt [768*256];
__device__ __half g_sWoT[256*256];

// ------------------------------ helpers -------------------------------------
__device__ __forceinline__ uint32_t su32(const void* p) {
    return (uint32_t)__cvta_generic_to_shared(p);
}
__device__ __forceinline__ uint32_t swz128(uint32_t o) {   // 128B-row swizzle
    return o ^ ((o >> 3) & 0x70);
}
__device__ __forceinline__ void cpa16(uint32_t saddr, const void* g) {
    asm volatile("cp.async.cg.shared.global [%0], [%1], 16;"
                 :: "r"(saddr), "l"(g));
}
__device__ __forceinline__ void ldm4(uint32_t* r, uint32_t addr) {
    asm volatile("ldmatrix.sync.aligned.m8n8.x4.shared.b16 {%0,%1,%2,%3}, [%4];"
                 : "=r"(r[0]), "=r"(r[1]), "=r"(r[2]), "=r"(r[3]) : "r"(addr));
}
__device__ __forceinline__ void mma16816h(float* d, const uint32_t* a,
                                          uint32_t b0, uint32_t b1) {
    asm volatile(
        "mma.sync.aligned.m16n8k16.row.col.f32.f16.f16.f32 "
        "{%0,%1,%2,%3}, {%4,%5,%6,%7}, {%8,%9}, {%0,%1,%2,%3};"
        : "+f"(d[0]), "+f"(d[1]), "+f"(d[2]), "+f"(d[3])
        : "r"(a[0]), "r"(a[1]), "r"(a[2]), "r"(a[3]), "r"(b0), "r"(b1));
}
__device__ __forceinline__ float wsum(float v) {
    v += __shfl_xor_sync(0xffffffffu, v, 16);
    v += __shfl_xor_sync(0xffffffffu, v, 8);
    v += __shfl_xor_sync(0xffffffffu, v, 4);
    v += __shfl_xor_sync(0xffffffffu, v, 2);
    v += __shfl_xor_sync(0xffffffffu, v, 1);
    return v;
}

// =========================== HMMA GEMM (128x128) ============================
// C[M,N] = (Ah+Al)[M,256] @ B^T + bias.   K chunks of 64, 2-stage cp.async.
// Warp tile 32x64: per k16 step 8 LDSM / 32 MMA.
#define STGB_  49152           // Ah 16K | Al 16K | B 16K per stage
#define GSMEM_DYN (2*STGB_ + 1024)

__global__ void __launch_bounds__(256, 2) gemm_mma(
    const __half* __restrict__ Ah,   // [M,256]
    const __half* __restrict__ Al,
    const __half* __restrict__ Bt,   // [N,256] K-major
    const float* __restrict__ bias,
    float* __restrict__ C, int ldc)
{
    extern __shared__ char smem_raw[];
    char* smem = (char*)(((uintptr_t)smem_raw + 1023) & ~(uintptr_t)1023);
    const uint32_t sbase = su32(smem);

    const int tid  = threadIdx.x;
    const int wid  = tid >> 5;
    const int lane = tid & 31;
    const int wm = wid & 3;         // 0..3  (32-row block)
    const int wn = wid >> 2;        // 0..1  (64-col block)
    const int m0 = blockIdx.y * 128;
    const int n0 = blockIdx.x * 128;

    const int frow = tid >> 3;      // 0..31
    const int fq   = tid & 7;       // 16B column within 128B row

    float acc[2][8][4];
    #pragma unroll
    for (int i = 0; i < 2; i++)
        #pragma unroll
        for (int j = 0; j < 8; j++)
            #pragma unroll
            for (int t = 0; t < 4; t++) acc[i][j][t] = 0.f;

    const int aR = lane & 15;
    const int aC16 = lane >> 4;
    const int bN = (lane & 7) + ((lane >> 1) & 8);
    const int bK8 = (lane >> 3) & 1;

    auto load_stage = [&](int c, int s) {
        uint32_t st = sbase + (uint32_t)s * STGB_;
        #pragma unroll
        for (int j = 0; j < 4; j++) {       // A hi: 128 rows
            int row = j * 32 + frow;
            uint32_t so = swz128(row * 128 + fq * 16);
            cpa16(st + so, Ah + (long)(m0 + row) * 256 + c * 64 + fq * 8);
        }
        #pragma unroll
        for (int j = 0; j < 4; j++) {       // A lo
            int row = j * 32 + frow;
            uint32_t so = swz128(row * 128 + fq * 16);
            cpa16(st + 16384u + so, Al + (long)(m0 + row) * 256 + c * 64 + fq * 8);
        }
        #pragma unroll
        for (int j = 0; j < 4; j++) {       // B
            int row = j * 32 + frow;
            uint32_t so = swz128(row * 128 + fq * 16);
            cpa16(st + 32768u + so, Bt + (long)(n0 + row) * 256 + c * 64 + fq * 8);
        }
    };

    load_stage(0, 0);
    asm volatile("cp.async.commit_group;" ::: "memory");

    for (int c = 0; c < 4; c++) {
        if (c + 1 < 4) {
            load_stage(c + 1, (c + 1) & 1);
            asm volatile("cp.async.commit_group;" ::: "memory");
            asm volatile("cp.async.wait_group 1;" ::: "memory");
        } else {
            asm volatile("cp.async.wait_group 0;" ::: "memory");
        }
        __syncthreads();

        const uint32_t st = sbase + (uint32_t)(c & 1) * STGB_;
        const uint32_t uAh = st, uAl = st + 16384u, uBt = st + 32768u;

        #pragma unroll
        for (int ks = 0; ks < 4; ks++) {
            uint32_t bf[4][4];
            #pragma unroll
            for (int ng = 0; ng < 4; ng++) {
                uint32_t boff = swz128((uint32_t)(wn * 64 + ng * 16 + bN) * 128
                                       + ks * 32 + bK8 * 16);
                ldm4(bf[ng], uBt + boff);
            }
            #pragma unroll
            for (int mt = 0; mt < 2; mt++) {
                uint32_t ah[4], al[4];
                uint32_t aoff = swz128((uint32_t)(wm * 32 + mt * 16 + aR) * 128
                                       + ks * 32 + aC16 * 16);
                ldm4(ah, uAh + aoff);
                ldm4(al, uAl + aoff);
                #pragma unroll
                for (int nt = 0; nt < 8; nt++) {
                    const int ng = nt >> 1, sb = (nt & 1) * 2;
                    mma16816h(acc[mt][nt], ah, bf[ng][sb], bf[ng][sb + 1]);
                    mma16816h(acc[mt][nt], al, bf[ng][sb], bf[ng][sb + 1]);
                }
            }
        }
        __syncthreads();
    }

    // ---- epilogue ----
    const int er = lane >> 2;
    const int ec = (lane & 3) * 2;
    #pragma unroll
    for (int mt = 0; mt < 2; mt++) {
        #pragma unroll
        for (int nt = 0; nt < 8; nt++) {
            const long m = m0 + wm * 32 + mt * 16 + er;
            const int  n = n0 + wn * 64 + nt * 8 + ec;
            float bx = bias[n], by = bias[n + 1];
            float2 o0, o1;
            o0.x = acc[mt][nt][0] + bx; o0.y = acc[mt][nt][1] + by;
            o1.x = acc[mt][nt][2] + bx; o1.y = acc[mt][nt][3] + by;
            *(float2*)(C + m * ldc + n) = o0;
            *(float2*)(C + (m + 8) * ldc + n) = o1;
        }
    }
}

// ============ fused Wo GEMM + bias + residual + relu + LN + split ===========
// Tile 64x256 (CTA owns full rows).  Stage: Ah 8K | Al 8K | B 32K = 48K.
#define LNSTR_ 264

__global__ void __launch_bounds__(256, 2) gemm_wo_ln(
    const __half* __restrict__ Ah,   // ctx hi  [M,256]
    const __half* __restrict__ Al,   // ctx lo
    const __half* __restrict__ Bt,   // WoT fp16 [256,256] K-major
    const float* __restrict__ bo,
    const float* __restrict__ res,   // residual fp32 [M,256]
    const float* __restrict__ lnw, const float* __restrict__ lnb,
    float* __restrict__ outF,
    __half* __restrict__ outH, __half* __restrict__ outL)
{
    extern __shared__ char smem_raw[];
    char* smem = (char*)(((uintptr_t)smem_raw + 1023) & ~(uintptr_t)1023);
    const uint32_t sbase = su32(smem);

    const int tid  = threadIdx.x;
    const int wid  = tid >> 5;
    const int lane = tid & 31;
    const int wm = wid >> 2;        // 0..1 (32-row block)
    const int wn = wid & 3;         // 0..3 (64-col block)
    const int m0 = blockIdx.x * 64;

    const int frow = tid >> 3;
    const int fq   = tid & 7;

    float acc[2][8][4];
    #pragma unroll
    for (int i = 0; i < 2; i++)
        #pragma unroll
        for (int j = 0; j < 8; j++)
            #pragma unroll
            for (int t = 0; t < 4; t++) acc[i][j][t] = 0.f;

    const int aR = lane & 15;
    const int aC16 = lane >> 4;
    const int bN = (lane & 7) + ((lane >> 1) & 8);
    const int bK8 = (lane >> 3) & 1;

    auto load_stage = [&](int c, int s) {
        uint32_t st = sbase + (uint32_t)s * STGB_;
        #pragma unroll
        for (int j = 0; j < 2; j++) {       // A hi: 64 rows
            int row = j * 32 + frow;
            uint32_t so = swz128(row * 128 + fq * 16);
            cpa16(st + so, Ah + (long)(m0 + row) * 256 + c * 64 + fq * 8);
        }
        #pragma unroll
        for (int j = 0; j < 2; j++) {       // A lo
            int row = j * 32 + frow;
            uint32_t so = swz128(row * 128 + fq * 16);
            cpa16(st + 8192u + so, Al + (long)(m0 + row) * 256 + c * 64 + fq * 8);
        }
        #pragma unroll
        for (int j = 0; j < 8; j++) {       // B: 256 rows
            int row = j * 32 + frow;
            uint32_t so = swz128(row * 128 + fq * 16);
            cpa16(st + 16384u + so, Bt + (long)row * 256 + c * 64 + fq * 8);
        }
    };

    load_stage(0, 0);
    asm volatile("cp.async.commit_group;" ::: "memory");

    for (int c = 0; c < 4; c++) {
        if (c + 1 < 4) {
            load_stage(c + 1, (c + 1) & 1);
            asm volatile("cp.async.commit_group;" ::: "memory");
            asm volatile("cp.async.wait_group 1;" ::: "memory");
        } else {
            asm volatile("cp.async.wait_group 0;" ::: "memory");
        }
        __syncthreads();

        const uint32_t st = sbase + (uint32_t)(c & 1) * STGB_;
        const uint32_t uAh = st, uAl = st + 8192u, uBt = st + 16384u;

        #pragma unroll
        for (int ks = 0; ks < 4; ks++) {
            uint32_t bf[4][4];
            #pragma unroll
            for (int ng = 0; ng < 4; ng++) {
                uint32_t boff = swz128((uint32_t)(wn * 64 + ng * 16 + bN) * 128
                                       + ks * 32 + bK8 * 16);
                ldm4(bf[ng], uBt + boff);
            }
            #pragma unroll
            for (int mt = 0; mt < 2; mt++) {
                uint32_t ah[4], al[4];
                uint32_t aoff = swz128((uint32_t)(wm * 32 + mt * 16 + aR) * 128
                                       + ks * 32 + aC16 * 16);
                ldm4(ah, uAh + aoff);
                ldm4(al, uAl + aoff);
                #pragma unroll
                for (int nt = 0; nt < 8; nt++) {
                    const int ng = nt >> 1, sb = (nt & 1) * 2;
                    mma16816h(acc[mt][nt], ah, bf[ng][sb], bf[ng][sb + 1]);
                    mma16816h(acc[mt][nt], al, bf[ng][sb], bf[ng][sb + 1]);
                }
            }
        }
        __syncthreads();
    }

    // ---- bias + residual + relu -> smem [64][LNSTR_] ----
    float* S = (float*)smem;
    const int er = lane >> 2;
    const int ec = (lane & 3) * 2;
    #pragma unroll
    for (int mt = 0; mt < 2; mt++) {
        #pragma unroll
        for (int nt = 0; nt < 8; nt++) {
            const int r0 = wm * 32 + mt * 16 + er;
            const int n = wn * 64 + nt * 8 + ec;
            const long m = m0 + r0;
            float bx = bo[n], by = bo[n + 1];
            float2 rr0 = *(const float2*)(res + m * 256 + n);
            float2 rr1 = *(const float2*)(res + (m + 8) * 256 + n);
            float2 o0, o1;
            o0.x = fmaxf(acc[mt][nt][0] + bx + rr0.x, 0.f);
            o0.y = fmaxf(acc[mt][nt][1] + by + rr0.y, 0.f);
            o1.x = fmaxf(acc[mt][nt][2] + bx + rr1.x, 0.f);
            o1.y = fmaxf(acc[mt][nt][3] + by + rr1.y, 0.f);
            *(float2*)&S[r0 * LNSTR_ + n] = o0;
            *(float2*)&S[(r0 + 8) * LNSTR_ + n] = o1;
        }
    }
    __syncthreads();

    // ---- per-row LayerNorm: warp w handles rows w, w+8, ..., w+56 ----
    #pragma unroll
    for (int rr = 0; rr < 8; rr++) {
        const int r = wid + rr * 8;
        float v[8], s1 = 0.f, s2 = 0.f;
        #pragma unroll
        for (int i = 0; i < 8; i++) {
            v[i] = S[r * LNSTR_ + lane + i * 32];
            s1 += v[i];
            s2 += v[i] * v[i];
        }
        s1 = wsum(s1); s2 = wsum(s2);
        float u = s1 * (1.f / 256.f);
        float var = s2 * (1.f / 256.f) - u * u;
        float inv = rsqrtf(var + 1e-12f);
        const long m = m0 + r;
        #pragma unroll
        for (int i = 0; i < 8; i++) {
            const int cc = lane + i * 32;
            float o = lnw[cc] * (v[i] - u) * inv + lnb[cc];
            outF[m * 256 + cc] = o;
            __half hh = __float2half_rn(o);
            outH[m * 256 + cc] = hh;
            outL[m * 256 + cc] = __float2half_rn(o - __half2float(hh));
        }
    }
}

// ------------------------- fp32 -> fp16 hi/lo split -------------------------
__global__ void __launch_bounds__(256) split_a(
    const float* __restrict__ a,
    __half* __restrict__ h, __half* __restrict__ l)
{
    int i = blockIdx.x * 256 + threadIdx.x;     // float4 index
    float4 v = ((const float4*)a)[i];
    __half hx = __float2half_rn(v.x);
    __half hy = __float2half_rn(v.y);
    __half hz = __float2half_rn(v.z);
    __half hw = __float2half_rn(v.w);
    __half2* hp = (__half2*)(h + i * 4);
    __half2* lp = (__half2*)(l + i * 4);
    __half2 h0; h0.x = hx; h0.y = hy;
    __half2 h1; h1.x = hz; h1.y = hw;
    __half2 l0, l1;
    l0.x = __float2half_rn(v.x - __half2float(hx));
    l0.y = __float2half_rn(v.y - __half2float(hy));
    l1.x = __float2half_rn(v.z - __half2float(hz));
    l1.y = __float2half_rn(v.w - __half2float(hw));
    hp[0] = h0; hp[1] = h1;
    lp[0] = l0; lp[1] = l1;
}

// ------------------------ all weight packs, one launch ----------------------
__global__ void __launch_bounds__(256) pack_all(
    const float* __restrict__ sWq, const float* __restrict__ sWk, const float* __restrict__ sWv,
    const float* __restrict__ sbq, const float* __restrict__ sbk, const float* __restrict__ sbv,
    const float* __restrict__ rWq, const float* __restrict__ rWk, const float* __restrict__ rWv,
    const float* __restrict__ rbq, const float* __restrict__ rbk, const float* __restrict__ rbv,
    const float* __restrict__ sWo,
    float* __restrict__ satW, float* __restrict__ satB,
    float* __restrict__ relW, float* __restrict__ relB,
    __half* __restrict__ sWt, __half* __restrict__ rWt, __half* __restrict__ sWoT)
{
    int blk = blockIdx.x;                 // 0..3327
    if (blk < 768) {                      // sat fp32 pack
        int idx = blk * 256 + threadIdx.x;
        int k = idx / 768, c = idx % 768;
        int sel = c >> 8, cc = c & 255;
        const float* W = (sel == 0) ? sWq : (sel == 1) ? sWk : sWv;
        satW[idx] = W[k * 256 + cc];
        if (idx < 768) {
            const float* b = (sel == 0) ? sbq : (sel == 1) ? sbk : sbv;
            satB[idx] = b[cc];
        }
    } else if (blk < 1536) {              // rel fp32 pack
        int idx = (blk - 768) * 256 + threadIdx.x;
        int k = idx / 768, c = idx % 768;
        int sel = c >> 8, cc = c & 255;
        const float* W = (sel == 0) ? rWq : (sel == 1) ? rWk : rWv;
        relW[idx] = W[k * 256 + cc];
        if (idx < 768) {
            const float* b = (sel == 0) ? rbq : (sel == 1) ? rbk : rbv;
            relB[idx] = b[cc];
        }
    } else if (blk < 2304) {              // sat fp16 transpose
        int idx = (blk - 1536) * 256 + threadIdx.x;
        int n = idx >> 8, k = idx & 255;
        int sel = n >> 8, nc = n & 255;
        const float* W = (sel == 0) ? sWq : (sel == 1) ? sWk : sWv;
        sWt[idx] = __float2half_rn(W[k * 256 + nc]);
    } else if (blk < 3072) {              // rel fp16 transpose
        int idx = (blk - 2304) * 256 + threadIdx.x;
        int n = idx >> 8, k = idx & 255;
        int sel = n >> 8, nc = n & 255;
        const float* W = (sel == 0) ? rWq : (sel == 1) ? rWk : rWv;
        rWt[idx] = __float2half_rn(W[k * 256 + nc]);
    } else {                              // Wo fp16 transpose
        int idx = (blk - 3072) * 256 + threadIdx.x;
        int n = idx >> 8, k = idx & 255;
        sWoT[idx] = __float2half_rn(sWo[k * 256 + n]);
    }
}

// ------------------------------ mean over L ---------------------------------
__global__ void __launch_bounds__(256) mean_stage1(const float* __restrict__ x,
                                                   float* __restrict__ part)
{
    int s = blockIdx.x, n = blockIdx.y, c = threadIdx.x;
    const float* base = x + ((long)n * L_ + (long)s * 128) * H_ + c;
    float sum = 0.f;
    #pragma unroll 8
    for (int l = 0; l < 128; l++) sum += base[(long)l * H_];
    part[(n * 32 + s) * H_ + c] = sum;
}

__global__ void __launch_bounds__(256) mean_stage2(const float* __restrict__ part,
                                                   float* __restrict__ center)
{
    int n = blockIdx.x, c = threadIdx.x;
    float sum = 0.f;
    #pragma unroll
    for (int s = 0; s < 32; s++) sum += part[(n * 32 + s) * H_ + c];
    center[n * H_ + c] = sum * (1.f / (float)L_);
}

// ---------------------- tiny projection: center @ Wpack ---------------------
__global__ void __launch_bounds__(256) cen_proj(
    const float* __restrict__ center, const float* __restrict__ Wp,
    const float* __restrict__ bp, float* __restrict__ out)
{
    __shared__ float sh[256];
    int idx = blockIdx.x * 256 + threadIdx.x;
    int r = idx / 768, c = idx % 768;
    sh[threadIdx.x] = center[r * 256 + threadIdx.x];
    __syncthreads();
    float s = bp[c];
    #pragma unroll 8
    for (int k = 0; k < 256; k++) s += sh[k] * Wp[k * 768 + c];
    out[idx] = s;
}

// --------------------------- sat attention ----------------------------------
// kvx = K/V of x taken from QKV(x) columns 256.. (stride 768).
__global__ void __launch_bounds__(256) sat_attn(
    const float* __restrict__ qkv,    // [NPOS,768] QKV of cur
    const float* __restrict__ kvx,    // = QKVx + 256, stride 768
    const float* __restrict__ cen,    // [B,768]
    __half* __restrict__ ctxH,
    __half* __restrict__ ctxL)
{
    int warp = (blockIdx.x * blockDim.x + threadIdx.x) >> 5;
    int lane = threadIdx.x & 31;
    if (warp >= NPOS) return;
    int n = warp >> 12;
    int l = warp & (L_ - 1);
    long i  = warp;
    long rb = (long)n * L_ + ((l + 1 == L_) ? 0 : l + 1);
    long ra = (long)n * L_ + ((l == 0) ? (L_ - 1) : 0);

    #pragma unroll
    for (int h = 0; h < 8; h++) {
        int off = h * 32 + lane;
        float qv = qkv[i * 768 + off];
        float k0 = qkv[rb * 768 + 256 + off];
        float k1 = qkv[i  * 768 + 256 + off];
        float k2 = qkv[ra * 768 + 256 + off];
        float k3 = kvx[i * 768 + off];
        float k4 = cen[n * 768 + 256 + off];
        float s0 = wsum(qv * k0) * SCALE_;
        float s1 = wsum(qv * k1) * SCALE_;
        float s2 = wsum(qv * k2) * SCALE_;
        float s3 = wsum(qv * k3) * SCALE_;
        float s4 = wsum(qv * k4) * SCALE_;
        float m = fmaxf(fmaxf(fmaxf(s0, s1), fmaxf(s2, s3)), s4);
        float p0 = __expf(s0 - m), p1 = __expf(s1 - m), p2 = __expf(s2 - m);
        float p3 = __expf(s3 - m), p4 = __expf(s4 - m);
        float den = p0 + p1 + p2 + p3 + p4;
        float v0 = qkv[rb * 768 + 512 + off];
        float v1 = qkv[i  * 768 + 512 + off];
        float v2 = qkv[ra * 768 + 512 + off];
        float v3 = kvx[i * 768 + 256 + off];
        float v4 = cen[n * 768 + 512 + off];
        float o = (p0 * v0 + p1 * v1 + p2 * v2 + p3 * v3 + p4 * v4) / den;
        __half hh = __float2half_rn(o);
        ctxH[i * 256 + off] = hh;
        ctxL[i * 256 + off] = __float2half_rn(o - __half2float(hh));
    }
}

// --------------------------- rel attention (split 8) ------------------------
#define RSPLIT_ 8
__global__ void __launch_bounds__(256) rel_attn_part(
    const float* __restrict__ cen,   // [B,768]
    const float* __restrict__ kvr,   // [NPOS,512]
    float* __restrict__ pm, float* __restrict__ ps, float* __restrict__ pacc)
{
    int blk = blockIdx.x;            // 64*8
    int sp = blk & 7;
    int nh = blk >> 3;
    int n = nh >> 3, h = nh & 7;
    int w = threadIdx.x >> 5, lane = threadIdx.x & 31;
    int off = h * 32 + lane;
    float qv = cen[n * 768 + off];
    int lo = sp * 512;
    int hi = (sp == RSPLIT_ - 1) ? (L_ + 1) : (sp + 1) * 512;
    float m = -1e30f, s = 0.f, acc = 0.f;
    for (int t = lo + w; t < hi; t += 8) {
        float kv, vv;
        if (t == 0) { kv = cen[n * 768 + 256 + off]; vv = cen[n * 768 + 512 + off]; }
        else {
            long r = (long)n * L_ + (t - 1);
            kv = kvr[r * 512 + off];
            vv = kvr[r * 512 + 256 + off];
        }
        float d = wsum(qv * kv) * SCALE_;
        float mn = fmaxf(m, d);
        float eo = __expf(m - mn);
        float en = __expf(d - mn);
        s = s * eo + en;
        acc = acc * eo + en * vv;
        m = mn;
    }
    __shared__ float sm[8], ss[8], sacc[8][32];
    sacc[w][lane] = acc;
    if (lane == 0) { sm[w] = m; ss[w] = s; }
    __syncthreads();
    if (w == 0) {
        float M = sm[0];
        #pragma unroll
        for (int r = 1; r < 8; r++) M = fmaxf(M, sm[r]);
        float S = 0.f, A = 0.f;
        #pragma unroll
        for (int r = 0; r < 8; r++) {
            float f = __expf(sm[r] - M);
            S += ss[r] * f;
            A += sacc[r][lane] * f;
        }
        if (lane == 0) { pm[blk] = M; ps[blk] = S; }
        pacc[blk * 32 + lane] = A;
    }
}

__global__ void __launch_bounds__(32) rel_attn_comb(
    const float* __restrict__ pm, const float* __restrict__ ps,
    const float* __restrict__ pacc, float* __restrict__ rctx)
{
    int nh = blockIdx.x;             // 0..63
    int n = nh >> 3, h = nh & 7;
    int lane = threadIdx.x;
    float M = -1e30f;
    #pragma unroll
    for (int sp = 0; sp < RSPLIT_; sp++) M = fmaxf(M, pm[nh * 8 + sp]);
    float S = 0.f, A = 0.f;
    #pragma unroll
    for (int sp = 0; sp < RSPLIT_; sp++) {
        float f = __expf(pm[nh * 8 + sp] - M);
        S += ps[nh * 8 + sp] * f;
        A += pacc[(nh * 8 + sp) * 32 + lane] * f;
    }
    rctx[n * 256 + h * 32 + lane] = A / S;
}

// ---------------- rel output: rctx@Wo + bo + center, relu, LN ---------------
__global__ void __launch_bounds__(256) rel_out(
    const float* __restrict__ rctx, const float* __restrict__ Wo,
    const float* __restrict__ bo, float* __restrict__ center,
    const float* __restrict__ lnw, const float* __restrict__ lnb)
{
    int n = blockIdx.x, c = threadIdx.x;
    __shared__ float sa[256];
    sa[c] = rctx[n * 256 + c];
    __syncthreads();
    float o = bo[c] + center[n * 256 + c];
    #pragma unroll 8
    for (int k = 0; k < 256; k++) o += sa[k] * Wo[k * 256 + c];
    o = fmaxf(o, 0.f);
    __shared__ float sh[16];
    int lane = c & 31, wid = c >> 5;
    float rs = wsum(o), rq = wsum(o * o);
    if (lane == 0) { sh[wid] = rs; sh[8 + wid] = rq; }
    __syncthreads();
    float ts = 0.f, tq = 0.f;
    #pragma unroll
    for (int i = 0; i < 8; i++) { ts += sh[i]; tq += sh[8 + i]; }
    float u = ts * (1.f / 256.f);
    float var = tq * (1.f / 256.f) - u * u;
    center[n * 256 + c] = lnw[c] * (o - u) * rsqrtf(var + 1e-12f) + lnb[c];
}

// ------------------------------- output tail --------------------------------
__global__ void write_tail(const float* __restrict__ center,
                           float* __restrict__ out, int ncur, int ntot)
{
    int i = ncur + blockIdx.x * 256 + threadIdx.x;
    if (i < ntot) {
        int j = i - ncur;
        out[i] = (j < B_ * H_) ? center[j] : 0.f;
    }
}

// ------------------------------- host side ----------------------------------
extern "C" void kernel_launch(void* const* d_in, const int* in_sizes, int n_in,
                              void* d_out, int out_size)
{
    const float* x    = (const float*)d_in[0];
    const float* sWq  = (const float*)d_in[1];
    const float* sbq  = (const float*)d_in[2];
    const float* sWk  = (const float*)d_in[3];
    const float* sbk  = (const float*)d_in[4];
    const float* sWv  = (const float*)d_in[5];
    const float* sbv  = (const float*)d_in[6];
    const float* sWo  = (const float*)d_in[7];
    const float* sbo  = (const float*)d_in[8];
    const float* rWq  = (const float*)d_in[9];
    const float* rbq  = (const float*)d_in[10];
    const float* rWk  = (const float*)d_in[11];
    const float* rbk  = (const float*)d_in[12];
    const float* rWv  = (const float*)d_in[13];
    const float* rbv  = (const float*)d_in[14];
    const float* rWo  = (const float*)d_in[15];
    const float* rbo  = (const float*)d_in[16];
    const float* slnw = (const float*)d_in[17];
    const float* slnb = (const float*)d_in[18];
    const float* rlnw = (const float*)d_in[19];
    const float* rlnb = (const float*)d_in[20];

    float *QKVx, *QKVc, *KVr, *cur, *center, *part;
    float *cenSat, *cenRel, *rctx, *satW, *relW, *satB, *relB;
    float *rpm, *rps, *rpacc;
    __half *xH, *xL, *ctxH, *ctxL, *curH, *curL, *sWt, *rWt, *sWoT;
    cudaGetSymbolAddress((void**)&QKVx,   g_QKVx);
    cudaGetSymbolAddress((void**)&QKVc,   g_QKVc);
    cudaGetSymbolAddress((void**)&KVr,    g_KVr);
    cudaGetSymbolAddress((void**)&cur,    g_cur);
    cudaGetSymbolAddress((void**)&center, g_center);
    cudaGetSymbolAddress((void**)&part,   g_part);
    cudaGetSymbolAddress((void**)&cenSat, g_cenSat);
    cudaGetSymbolAddress((void**)&cenRel, g_cenRel);
    cudaGetSymbolAddress((void**)&rctx,   g_rctx);
    cudaGetSymbolAddress((void**)&rpm,    g_rpm);
    cudaGetSymbolAddress((void**)&rps,    g_rps);
    cudaGetSymbolAddress((void**)&rpacc,  g_rpacc);
    cudaGetSymbolAddress((void**)&satW,   g_satW);
    cudaGetSymbolAddress((void**)&relW,   g_relW);
    cudaGetSymbolAddress((void**)&satB,   g_satBias);
    cudaGetSymbolAddress((void**)&relB,   g_relBias);
    cudaGetSymbolAddress((void**)&xH,     g_xH);
    cudaGetSymbolAddress((void**)&xL,     g_xL);
    cudaGetSymbolAddress((void**)&ctxH,   g_ctxH);
    cudaGetSymbolAddress((void**)&ctxL,   g_ctxL);
    cudaGetSymbolAddress((void**)&curH,   g_curH);
    cudaGetSymbolAddress((void**)&curL,   g_curL);
    cudaGetSymbolAddress((void**)&sWt,    g_sWt);
    cudaGetSymbolAddress((void**)&rWt,    g_rWt);
    cudaGetSymbolAddress((void**)&sWoT,   g_sWoT);

    cudaFuncSetAttribute(gemm_mma, cudaFuncAttributeMaxDynamicSharedMemorySize, GSMEM_DYN);
    cudaFuncSetAttribute(gemm_wo_ln, cudaFuncAttributeMaxDynamicSharedMemorySize, GSMEM_DYN);

    // launches 1-3, then gemm_mma is the 4th (ncu captures #4)
    pack_all<<<3328, 256>>>(sWq, sWk, sWv, sbq, sbk, sbv,
                            rWq, rWk, rWv, rbq, rbk, rbv, sWo,
                            satW, satB, relW, relB, sWt, rWt, sWoT);
    split_a<<<NPOS * 256 / 1024, 256>>>(x, xH, xL);
    mean_stage1<<<dim3(32, B_), 256>>>(x, part);

    // QKV of x — serves as iter-0 QKV(cur) AND K/V(x) for both iterations
    gemm_mma<<<dim3(6, NPOS / 128), 256, GSMEM_DYN>>>(
        xH, xL, sWt, satB, QKVx, 768);

    mean_stage2<<<B_, 256>>>(part, center);

    for (int it = 0; it < 2; it++) {
        const float* resf = (it == 0) ? x : cur;
        float* lnDst = (it == 0) ? cur : (float*)d_out;
        const float* qkvCur = (it == 0) ? QKVx : QKVc;

        cen_proj<<<24, 256>>>(center, satW, satB, cenSat);
        if (it == 1) {
            gemm_mma<<<dim3(6, NPOS / 128), 256, GSMEM_DYN>>>(
                curH, curL, sWt, satB, QKVc, 768);
        }
        sat_attn<<<NPOS / 8, 256>>>(qkvCur, QKVx + 256, cenSat, ctxH, ctxL);
        gemm_wo_ln<<<NPOS / 64, 256, GSMEM_DYN>>>(
            ctxH, ctxL, sWoT, sbo, resf, slnw, slnb, lnDst, curH, curL);

        cen_proj<<<24, 256>>>(center, relW, relB, cenRel);
        gemm_mma<<<dim3(4, NPOS / 128), 256, GSMEM_DYN>>>(
            curH, curL, rWt + 256 * 256, relB + 256, KVr, 512);
        rel_attn_part<<<64 * RSPLIT_, 256>>>(cenRel, KVr, rpm, rps, rpacc);
        rel_attn_comb<<<64, 32>>>(rpm, rps, rpacc, rctx);
        rel_out<<<B_, 256>>>(rctx, rWo, rbo, center, rlnw, rlnb);
    }

    int ncur = NPOS * H_;
    int tail = out_size - ncur;
    if (tail > 0)
        write_tail<<<(tail + 255) / 256, 256>>>(center, (float*)d_out, ncur, out_size);
}